// round 10
// baseline (speedup 1.0000x reference)
#include <cuda_runtime.h>
#include <math.h>

#define D_DIM   1024
#define E_DIM   64
#define TOPK    8
#define BM      128
#define BK      8
#define NTILES  (D_DIM / BK)          // 128
#define TILES_PER_CHUNK 32            // 256-k chunks (reference-matching)
#define NTHREADS 256
#define XS_STRIDE 12                  // floats per x row (8 data + 4 pad)
#define XBUF_FLOATS (BM * XS_STRIDE)            // 1536
#define WS_KSTRIDE 80                 // 4 expert-groups at +20 floats
#define WBUF_FLOATS (BK * WS_KSTRIDE)           // 640
#define BUF_FLOATS (XBUF_FLOATS + WBUF_FLOATS)  // 2176
#define LS_STRIDE 66                  // epilogue overlay stride
#define SMEM_FLOATS (BM * LS_STRIDE)  // 8448 (> 2*BUF_FLOATS)

// global scratch (allocation-free per harness rules)
__device__ int   g_counts[E_DIM];
__device__ int   g_done;
__device__ float Wt[D_DIM * E_DIM];   // W transposed: Wt[k][e]

__device__ __forceinline__ unsigned long long pack2(float a, float b) {
    unsigned long long r;
    asm("mov.b64 %0, {%1, %2};" : "=l"(r) : "f"(a), "f"(b));
    return r;
}
__device__ __forceinline__ void fma2(unsigned long long& d,
                                     unsigned long long a,
                                     unsigned long long b) {
    // packed 2x fp32 FMA (per-lane IEEE fp32) -- same math as scalar FFMA
    asm("fma.rn.f32x2 %0, %1, %2, %3;" : "=l"(d) : "l"(a), "l"(b), "l"(d));
}
__device__ __forceinline__ void add2(unsigned long long& d,
                                     unsigned long long a) {
    asm("add.rn.f32x2 %0, %0, %1;" : "+l"(d) : "l"(a));
}
__device__ __forceinline__ void cpa16(unsigned dst, const float* src) {
    asm volatile("cp.async.cg.shared.global [%0], [%1], 16;"
                 :: "r"(dst), "l"(src));
}

// One-shot (per launch) W transpose: read coalesced along k, write [k][e].
__global__ void transpose_w_kernel(const float* __restrict__ W) {
    int idx = blockIdx.x * blockDim.x + threadIdx.x;   // = e*D + k
    int e = idx >> 10, k = idx & (D_DIM - 1);
    Wt[k * E_DIM + e] = W[idx];
}

__global__ __launch_bounds__(NTHREADS, 2)
void gate_kernel(const float* __restrict__ x, const float* __restrict__ b,
                 const float* __restrict__ eu,
                 float* __restrict__ out_idx, float* __restrict__ out_gate,
                 float* __restrict__ out_var, float invN) {
    extern __shared__ __align__(16) float pool[];
    __shared__ float bsh[E_DIM];
    __shared__ int hist[E_DIM];
    __shared__ int lastFlag;

    float* Ls = pool;                 // epilogue overlay of the buffers

    const int tid = threadIdx.x;
    const int tx  = tid & 3;          // experts tx*16 .. tx*16+15
    const int ty  = tid >> 2;         // rows ty and ty+64
    const int row0 = blockIdx.x * BM;

    if (tid < E_DIM) { bsh[tid] = b[tid]; hist[tid] = 0; }

    unsigned long long acc[2][8];     // current 256-k chunk partial
    unsigned long long tot[2][8];     // running total ((P0+P1)+P2)+P3
#pragma unroll
    for (int r = 0; r < 2; r++)
#pragma unroll
        for (int j = 0; j < 8; j++) { acc[r][j] = 0ULL; tot[r][j] = 0ULL; }

    // ---- cp.async staging maps (fixed per thread) ----
    // x: 256 16B-chunks per tile, exactly one per thread
    const int xrow = tid >> 1, xc = (tid & 1) << 2;
    const float* xsrc = x + (size_t)(row0 + xrow) * D_DIM + xc;
    const unsigned xdst = (unsigned)((xrow * XS_STRIDE + xc) * 4);
    // w: 128 16B data-chunks per tile, threads 0..127
    const int wk = tid >> 4, wg = (tid >> 2) & 3, wi = tid & 3;
    const float* wsrc = Wt + (size_t)wk * E_DIM + wg * 16 + wi * 4;
    const unsigned wdst = (unsigned)((wk * WS_KSTRIDE + wg * 20 + wi * 4) * 4);
    const bool do_w = (tid < 128);

    const unsigned smem0 = (unsigned)__cvta_generic_to_shared(pool);

    // preload tile 0
    cpa16(smem0 + xdst, xsrc);
    if (do_w) cpa16(smem0 + XBUF_FLOATS * 4 + wdst, wsrc);
    asm volatile("cp.async.commit_group;" ::: "memory");

#pragma unroll 1
    for (int tile = 0; tile < NTILES; tile++) {
        if (tile + 1 < NTILES) {
            const int kb = (tile + 1) * BK;
            const unsigned base = smem0 + ((tile + 1) & 1) * (BUF_FLOATS * 4);
            cpa16(base + xdst, xsrc + kb);
            if (do_w)
                cpa16(base + XBUF_FLOATS * 4 + wdst, wsrc + (size_t)kb * E_DIM);
            asm volatile("cp.async.commit_group;" ::: "memory");
            asm volatile("cp.async.wait_group 1;" ::: "memory");
        } else {
            asm volatile("cp.async.wait_group 0;" ::: "memory");
        }
        __syncthreads();   // tile's data visible to all threads

        const float* xsb = pool + (tile & 1) * BUF_FLOATS;
        const float* wsb = xsb + XBUF_FLOATS;
        // ---- compute: per k: 2 LDS.32(x) + 4 LDS.128(w) + 16 FFMA2 ----
#pragma unroll
        for (int k = 0; k < BK; k++) {
            const unsigned long long* wr8 =
                (const unsigned long long*)(wsb + k * WS_KSTRIDE + tx * 20);
            ulonglong2 w0 = *(const ulonglong2*)(wr8 + 0);
            ulonglong2 w1 = *(const ulonglong2*)(wr8 + 2);
            ulonglong2 w2 = *(const ulonglong2*)(wr8 + 4);
            ulonglong2 w3 = *(const ulonglong2*)(wr8 + 6);
#pragma unroll
            for (int r = 0; r < 2; r++) {
                float xv = xsb[(r * 64 + ty) * XS_STRIDE + k];
                unsigned long long xd = pack2(xv, xv);
                fma2(acc[r][0], xd, w0.x); fma2(acc[r][1], xd, w0.y);
                fma2(acc[r][2], xd, w1.x); fma2(acc[r][3], xd, w1.y);
                fma2(acc[r][4], xd, w2.x); fma2(acc[r][5], xd, w2.y);
                fma2(acc[r][6], xd, w3.x); fma2(acc[r][7], xd, w3.y);
            }
        }
        // ---- 256-k chunk folds: tot = ((P0+P1)+P2)+P3 (registers) ----
        if ((tile & (TILES_PER_CHUNK - 1)) == (TILES_PER_CHUNK - 1)) {
#pragma unroll
            for (int r = 0; r < 2; r++)
#pragma unroll
                for (int j = 0; j < 8; j++) {
                    add2(tot[r][j], acc[r][j]);
                    acc[r][j] = 0ULL;
                }
        }
        __syncthreads();   // all consumers done before buffer reuse
    }
    __syncthreads();

    // ---- spill biased logits: Ls[row][expert], stride 66 ----
#pragma unroll
    for (int r = 0; r < 2; r++) {
        int row = r * 64 + ty;
#pragma unroll
        for (int j = 0; j < 8; j++) {
            int ec = tx * 16 + j * 2;
            float lo = __uint_as_float((unsigned)(tot[r][j] & 0xffffffffULL));
            float hi = __uint_as_float((unsigned)(tot[r][j] >> 32));
            Ls[(size_t)row * LS_STRIDE + ec]     = lo + bsh[ec];
            Ls[(size_t)row * LS_STRIDE + ec + 1] = hi + bsh[ec + 1];
        }
    }
    __syncthreads();

    if (tid < BM) {
        const int row = row0 + tid;
        float* L = Ls + (size_t)tid * LS_STRIDE;
        float mx = L[0];
#pragma unroll
        for (int e = 1; e < E_DIM; e++) mx = fmaxf(mx, L[e]);
        float s = 0.f;
#pragma unroll
        for (int e = 0; e < E_DIM; e++) s += expf(L[e] - mx);
        float inv = 1.f / s;
        // top-8 by raw logits; strict >, lowest index ties (lax.top_k)
        const float NEG_INF = __int_as_float(0xff800000);
        unsigned long long used = 0ULL;
        float gv[TOPK]; int gi[TOPK];
        float gs = 0.f;
#pragma unroll
        for (int j = 0; j < TOPK; j++) {
            float best = NEG_INF; int bi = 0;
            for (int e = 0; e < E_DIM; e++) {
                float v = L[e];
                if (!((used >> e) & 1ULL) && v > best) { best = v; bi = e; }
            }
            used |= (1ULL << bi);
            float g = expf(best - mx) * inv;
            gv[j] = g; gi[j] = bi; gs += g;
            atomicAdd(&hist[bi], 1);
        }
        float rn = 1.f / (gs + 1e-8f);
#pragma unroll
        for (int j = 0; j < TOPK; j++) {
            out_idx[(size_t)row * TOPK + j]  = (float)gi[j];
            out_gate[(size_t)row * TOPK + j] = gv[j] * rn;
        }
    }
    __syncthreads();
    if (tid < E_DIM) atomicAdd(&g_counts[tid], hist[tid]);

    // ---- fused finisher: last CTA computes EMA-usage variance ----
    __syncthreads();
    if (tid == 0) {
        __threadfence();
        int old = atomicAdd(&g_done, 1);
        lastFlag = (old == (int)gridDim.x - 1);
    }
    __syncthreads();
    if (lastFlag && tid == 0) {
        float u[E_DIM];
        float m = 0.f;
        for (int e = 0; e < E_DIM; e++) {
            int c = atomicExch(&g_counts[e], 0);   // read + reset for replay
            u[e] = 0.95f * eu[e] + 0.05f * ((float)c * invN);
            m += u[e];
        }
        m *= (1.f / E_DIM);
        float v = 0.f;
        for (int e = 0; e < E_DIM; e++) {
            float d = u[e] - m;
            v += d * d;
        }
        *out_var = v * (1.f / (E_DIM - 1));   // ddof=1
        atomicExch(&g_done, 0);               // reset for next replay
    }
}

extern "C" void kernel_launch(void* const* d_in, const int* in_sizes, int n_in,
                              void* d_out, int out_size) {
    const float* x  = (const float*)d_in[0];
    const float* W  = (const float*)d_in[1];
    const float* b  = (const float*)d_in[2];
    const float* eu = (const float*)d_in[3];
    const int N = in_sizes[0] / D_DIM;   // 262144

    float* out      = (float*)d_out;
    float* out_idx  = out;                        // [N,8] indices (as float)
    float* out_gate = out + (size_t)N * TOPK;     // [N,8] gates
    float* out_var  = out + (out_size - 1);       // scalar variance

    static int smem_set = 0;
    if (!smem_set) {
        cudaFuncSetAttribute(gate_kernel,
                             cudaFuncAttributeMaxDynamicSharedMemorySize,
                             SMEM_FLOATS * 4);
        smem_set = 1;
    }

    transpose_w_kernel<<<(E_DIM * D_DIM) / 256, 256>>>(W);
    gate_kernel<<<N / BM, NTHREADS, SMEM_FLOATS * 4>>>(
        x, b, eu, out_idx, out_gate, out_var, 1.f / (float)N);
}

// round 11
// speedup vs baseline: 1.0615x; 1.0615x over previous
#include <cuda_runtime.h>
#include <math.h>

#define D_DIM   1024
#define E_DIM   64
#define TOPK    8
#define BM      256
#define BK      16
#define NTILES  (D_DIM / BK)          // 64
#define NTHREADS 128
#define XS_STRIDE 20                  // 16 data + 4 pad (16B-aligned rows)
#define XBUF_FLOATS (BM * XS_STRIDE)            // 5120
#define WS_KSTRIDE 80                 // 4 expert-groups at +20 floats
#define WBUF_FLOATS (BK * WS_KSTRIDE)           // 1280
#define BUF_FLOATS (XBUF_FLOATS + WBUF_FLOATS)  // 6400
#define LS_STRIDE 66
#define SMEM_FLOATS (BM * LS_STRIDE)  // 16896 (> 2*BUF_FLOATS)
#define GAP_TAU 1e-4f

// global scratch (allocation-free per harness rules)
__device__ int   g_counts[E_DIM];
__device__ int   g_done;
__device__ float Wt[D_DIM * E_DIM];   // W transposed: Wt[k][e]

__device__ __forceinline__ unsigned long long pack2(float a, float b) {
    unsigned long long r;
    asm("mov.b64 %0, {%1, %2};" : "=l"(r) : "f"(a), "f"(b));
    return r;
}
__device__ __forceinline__ void fma2(unsigned long long& d,
                                     unsigned long long a,
                                     unsigned long long b) {
    asm("fma.rn.f32x2 %0, %1, %2, %3;" : "=l"(d) : "l"(a), "l"(b), "l"(d));
}
__device__ __forceinline__ void cpa16(unsigned dst, const float* src) {
    asm volatile("cp.async.cg.shared.global [%0], [%1], 16;"
                 :: "r"(dst), "l"(src));
}

__global__ void transpose_w_kernel(const float* __restrict__ W) {
    int idx = blockIdx.x * blockDim.x + threadIdx.x;   // = e*D + k
    int e = idx >> 10, k = idx & (D_DIM - 1);
    Wt[k * E_DIM + e] = W[idx];
}

__global__ __launch_bounds__(NTHREADS, 2)
void gate_kernel(const float* __restrict__ x, const float* __restrict__ b,
                 const float* __restrict__ eu,
                 float* __restrict__ out_idx, float* __restrict__ out_gate,
                 float* __restrict__ out_var, float invN) {
    extern __shared__ __align__(16) float pool[];
    __shared__ float bsh[E_DIM];
    __shared__ int hist[E_DIM];
    __shared__ int flagList[64];
    __shared__ int flagCnt;
    __shared__ int lastFlag;

    float* Ls = pool;                 // epilogue overlay

    const int tid = threadIdx.x;
    const int tx  = tid & 3;          // experts tx*16 .. tx*16+15
    const int ty  = tid >> 2;         // 32 row-groups; rows = r*32 + ty
    const int row0 = blockIdx.x * BM;

    if (tid < E_DIM) { bsh[tid] = b[tid]; hist[tid] = 0; }
    if (tid == 0) flagCnt = 0;

    unsigned long long acc[8][8];     // plain sequential fp32 accumulation
#pragma unroll
    for (int r = 0; r < 8; r++)
#pragma unroll
        for (int j = 0; j < 8; j++) acc[r][j] = 0ULL;

    // ---- cp.async maps ----
    // x: 1024 16B chunks/tile; thread i handles rows ty+32i (i=0..7), col tx*4
    const float* xbase = x + (size_t)(row0 + ty) * D_DIM + tx * 4;
    // w: 256 chunks/tile; thread handles krows (tid>>4)+8i (i=0,1), seg tid&15
    const int wkr = tid >> 4, wseg = tid & 15;
    const float* wbase = Wt + (size_t)wkr * E_DIM + wseg * 4;
    const unsigned wdo = (unsigned)((wkr * WS_KSTRIDE
                       + ((wseg >> 2) * 20) + ((wseg & 3) * 4)) * 4);
    const unsigned xdo = (unsigned)((ty * XS_STRIDE + tx * 4) * 4);
    const unsigned smem0 = (unsigned)__cvta_generic_to_shared(pool);

    // preload tile 0
#pragma unroll
    for (int i = 0; i < 8; i++)
        cpa16(smem0 + xdo + i * (32 * XS_STRIDE * 4),
              xbase + (size_t)i * 32 * D_DIM);
#pragma unroll
    for (int i = 0; i < 2; i++)
        cpa16(smem0 + XBUF_FLOATS * 4 + wdo + i * (8 * WS_KSTRIDE * 4),
              wbase + (size_t)i * 8 * E_DIM);
    asm volatile("cp.async.commit_group;" ::: "memory");

#pragma unroll 1
    for (int tile = 0; tile < NTILES; tile++) {
        if (tile + 1 < NTILES) {
            const int kb = (tile + 1) * BK;
            const unsigned base = smem0 + ((tile + 1) & 1) * (BUF_FLOATS * 4);
#pragma unroll
            for (int i = 0; i < 8; i++)
                cpa16(base + xdo + i * (32 * XS_STRIDE * 4),
                      xbase + kb + (size_t)i * 32 * D_DIM);
#pragma unroll
            for (int i = 0; i < 2; i++)
                cpa16(base + XBUF_FLOATS * 4 + wdo + i * (8 * WS_KSTRIDE * 4),
                      wbase + ((size_t)kb + i * 8) * E_DIM);
            asm volatile("cp.async.commit_group;" ::: "memory");
            asm volatile("cp.async.wait_group 1;" ::: "memory");
        } else {
            asm volatile("cp.async.wait_group 0;" ::: "memory");
        }
        __syncthreads();

        const float* xsb = pool + (tile & 1) * BUF_FLOATS;
        const float* wsb = xsb + XBUF_FLOATS;
#pragma unroll 2
        for (int k = 0; k < BK; k++) {
            const unsigned long long* wr8 =
                (const unsigned long long*)(wsb + k * WS_KSTRIDE + tx * 20);
            ulonglong2 w0 = *(const ulonglong2*)(wr8 + 0);
            ulonglong2 w1 = *(const ulonglong2*)(wr8 + 2);
            ulonglong2 w2 = *(const ulonglong2*)(wr8 + 4);
            ulonglong2 w3 = *(const ulonglong2*)(wr8 + 6);
#pragma unroll
            for (int r = 0; r < 8; r++) {
                float xv = xsb[(r * 32 + ty) * XS_STRIDE + k];
                unsigned long long xd = pack2(xv, xv);
                fma2(acc[r][0], xd, w0.x); fma2(acc[r][1], xd, w0.y);
                fma2(acc[r][2], xd, w1.x); fma2(acc[r][3], xd, w1.y);
                fma2(acc[r][4], xd, w2.x); fma2(acc[r][5], xd, w2.y);
                fma2(acc[r][6], xd, w3.x); fma2(acc[r][7], xd, w3.y);
            }
        }
        __syncthreads();   // all consumers done before buffer reuse
    }

    // ---- spill biased logits: Ls[row][expert], stride 66 ----
#pragma unroll
    for (int r = 0; r < 8; r++) {
        int row = r * 32 + ty;
#pragma unroll
        for (int j = 0; j < 8; j++) {
            int ec = tx * 16 + j * 2;
            float lo = __uint_as_float((unsigned)(acc[r][j] & 0xffffffffULL));
            float hi = __uint_as_float((unsigned)(acc[r][j] >> 32));
            Ls[(size_t)row * LS_STRIDE + ec]     = lo + bsh[ec];
            Ls[(size_t)row * LS_STRIDE + ec + 1] = hi + bsh[ec + 1];
        }
    }
    __syncthreads();

    const float NEG_INF = __int_as_float(0xff800000);
#pragma unroll 1
    for (int half = 0; half < 2; half++) {
        const int lrow = tid + half * 128;
        const int row = row0 + lrow;
        float* L = Ls + (size_t)lrow * LS_STRIDE;
        float mx = L[0];
#pragma unroll
        for (int e = 1; e < E_DIM; e++) mx = fmaxf(mx, L[e]);
        float s = 0.f;
#pragma unroll
        for (int e = 0; e < E_DIM; e++) s += expf(L[e] - mx);
        float inv = 1.f / s;
        // top-9 by raw logits (strict >, lowest index ties)
        float tv[TOPK + 1]; int ti[TOPK + 1];
        unsigned long long used = 0ULL;
#pragma unroll
        for (int j = 0; j < TOPK + 1; j++) {
            float best = NEG_INF; int bi = 0;
            for (int e = 0; e < E_DIM; e++) {
                float v = L[e];
                if (!((used >> e) & 1ULL) && v > best) { best = v; bi = e; }
            }
            used |= (1ULL << bi);
            tv[j] = best; ti[j] = bi;
        }
        bool close = false;
#pragma unroll
        for (int j = 0; j < TOPK; j++)
            close |= (tv[j] - tv[j + 1]) < GAP_TAU;

        int fidx = -1;
        if (close) {
            fidx = atomicAdd(&flagCnt, 1);
            if (fidx < 64) flagList[fidx] = lrow;
        }
        if (!close || fidx >= 64) {
            float gs = 0.f, gv[TOPK];
#pragma unroll
            for (int j = 0; j < TOPK; j++) {
                float g = expf(tv[j] - mx) * inv;
                gv[j] = g; gs += g;
                atomicAdd(&hist[ti[j]], 1);
            }
            float rn = 1.f / (gs + 1e-8f);
#pragma unroll
            for (int j = 0; j < TOPK; j++) {
                out_idx[(size_t)row * TOPK + j]  = (float)ti[j];
                out_gate[(size_t)row * TOPK + j] = gv[j] * rn;
            }
        }
    }
    __syncthreads();

    // ---- exact refine of flagged rows (chunk-256, matches reference) ----
    {
        const int wid = tid >> 5, lane = tid & 31;
        const int nflag = min(flagCnt, 64);
        for (int fi = wid; fi < nflag; fi += 4) {
            const int lrow = flagList[fi];
            const float* xr = x + (size_t)(row0 + lrow) * D_DIM;
            float tot0 = 0.f, tot1 = 0.f;
#pragma unroll 1
            for (int ch = 0; ch < 4; ch++) {
                float s0 = 0.f, s1 = 0.f;
                const float* xp = xr + ch * 256;
                const float* wp = Wt + (size_t)(ch * 256) * E_DIM;
#pragma unroll 4
                for (int k2 = 0; k2 < 256; k2++) {
                    float xv = __ldg(xp + k2);
                    s0 = fmaf(xv, __ldg(wp + k2 * E_DIM + lane), s0);
                    s1 = fmaf(xv, __ldg(wp + k2 * E_DIM + lane + 32), s1);
                }
                if (ch == 0) { tot0 = s0; tot1 = s1; }
                else         { tot0 += s0; tot1 += s1; }
            }
            float* L = Ls + (size_t)lrow * LS_STRIDE;
            L[lane]      = tot0 + bsh[lane];
            L[lane + 32] = tot1 + bsh[lane + 32];
            __syncwarp();
            if (lane == 0) {
                const int row = row0 + lrow;
                float mx = L[0];
                for (int e = 1; e < E_DIM; e++) mx = fmaxf(mx, L[e]);
                float s = 0.f;
                for (int e = 0; e < E_DIM; e++) s += expf(L[e] - mx);
                float inv = 1.f / s;
                unsigned long long used = 0ULL;
                float gs = 0.f, gv[TOPK]; int gi[TOPK];
                for (int j = 0; j < TOPK; j++) {
                    float best = NEG_INF; int bi = 0;
                    for (int e = 0; e < E_DIM; e++) {
                        float v = L[e];
                        if (!((used >> e) & 1ULL) && v > best) { best = v; bi = e; }
                    }
                    used |= (1ULL << bi);
                    float g = expf(best - mx) * inv;
                    gv[j] = g; gi[j] = bi; gs += g;
                    atomicAdd(&hist[bi], 1);
                }
                float rn = 1.f / (gs + 1e-8f);
                for (int j = 0; j < TOPK; j++) {
                    out_idx[(size_t)row * TOPK + j]  = (float)gi[j];
                    out_gate[(size_t)row * TOPK + j] = gv[j] * rn;
                }
            }
            __syncwarp();
        }
    }
    __syncthreads();
    if (tid < E_DIM) atomicAdd(&g_counts[tid], hist[tid]);

    // ---- fused finisher: last CTA computes EMA-usage variance ----
    __syncthreads();
    if (tid == 0) {
        __threadfence();
        int old = atomicAdd(&g_done, 1);
        lastFlag = (old == (int)gridDim.x - 1);
    }
    __syncthreads();
    if (lastFlag && tid == 0) {
        float u[E_DIM];
        float m = 0.f;
        for (int e = 0; e < E_DIM; e++) {
            int c = atomicExch(&g_counts[e], 0);   // read + reset for replay
            u[e] = 0.95f * eu[e] + 0.05f * ((float)c * invN);
            m += u[e];
        }
        m *= (1.f / E_DIM);
        float v = 0.f;
        for (int e = 0; e < E_DIM; e++) {
            float d = u[e] - m;
            v += d * d;
        }
        *out_var = v * (1.f / (E_DIM - 1));   // ddof=1
        atomicExch(&g_done, 0);               // reset for next replay
    }
}

extern "C" void kernel_launch(void* const* d_in, const int* in_sizes, int n_in,
                              void* d_out, int out_size) {
    const float* x  = (const float*)d_in[0];
    const float* W  = (const float*)d_in[1];
    const float* b  = (const float*)d_in[2];
    const float* eu = (const float*)d_in[3];
    const int N = in_sizes[0] / D_DIM;   // 262144

    float* out      = (float*)d_out;
    float* out_idx  = out;                        // [N,8] indices (as float)
    float* out_gate = out + (size_t)N * TOPK;     // [N,8] gates
    float* out_var  = out + (out_size - 1);       // scalar variance

    static int smem_set = 0;
    if (!smem_set) {
        cudaFuncSetAttribute(gate_kernel,
                             cudaFuncAttributeMaxDynamicSharedMemorySize,
                             SMEM_FLOATS * 4);
        smem_set = 1;
    }

    transpose_w_kernel<<<(E_DIM * D_DIM) / 256, 256>>>(W);
    gate_kernel<<<N / BM, NTHREADS, SMEM_FLOATS * 4>>>(
        x, b, eu, out_idx, out_gate, out_var, 1.f / (float)N);
}

// round 12
// speedup vs baseline: 1.1930x; 1.1239x over previous
#include <cuda_runtime.h>
#include <math.h>

#define D_DIM   1024
#define E_DIM   64
#define TOPK    8
#define BM      256
#define BK      8
#define NTILES  (D_DIM / BK)          // 128
#define NTHREADS 256
#define XS_STRIDE 12                  // 8 data + 4 pad floats per row
#define XBUF_FLOATS (BM * XS_STRIDE)            // 3072
#define WS_KSTRIDE 80                 // 4 expert-groups at +20 floats
#define WBUF_FLOATS (BK * WS_KSTRIDE)           // 640
#define BUF_FLOATS (XBUF_FLOATS + WBUF_FLOATS)  // 3712
#define LS_STRIDE 66
#define SMEM_FLOATS (BM * LS_STRIDE)  // 16896 (> 2*BUF_FLOATS)
#define GAP_TAU 1e-4f

// global scratch (allocation-free per harness rules)
__device__ int   g_counts[E_DIM];
__device__ int   g_done;
__device__ float Wt[D_DIM * E_DIM];   // W transposed: Wt[k][e]

__device__ __forceinline__ unsigned long long pack2(float a, float b) {
    unsigned long long r;
    asm("mov.b64 %0, {%1, %2};" : "=l"(r) : "f"(a), "f"(b));
    return r;
}
__device__ __forceinline__ void fma2(unsigned long long& d,
                                     unsigned long long a,
                                     unsigned long long b) {
    asm("fma.rn.f32x2 %0, %1, %2, %3;" : "=l"(d) : "l"(a), "l"(b), "l"(d));
}
__device__ __forceinline__ void cpa16(unsigned dst, const float* src) {
    asm volatile("cp.async.cg.shared.global [%0], [%1], 16;"
                 :: "r"(dst), "l"(src));
}

__global__ void transpose_w_kernel(const float* __restrict__ W) {
    int idx = blockIdx.x * blockDim.x + threadIdx.x;   // = e*D + k
    int e = idx >> 10, k = idx & (D_DIM - 1);
    Wt[k * E_DIM + e] = W[idx];
}

__global__ __launch_bounds__(NTHREADS, 2)
void gate_kernel(const float* __restrict__ x, const float* __restrict__ b,
                 const float* __restrict__ eu,
                 float* __restrict__ out_idx, float* __restrict__ out_gate,
                 float* __restrict__ out_var, float invN) {
    extern __shared__ __align__(16) float pool[];
    __shared__ float bsh[E_DIM];
    __shared__ int hist[E_DIM];
    __shared__ int flagList[64];
    __shared__ int flagCnt;
    __shared__ int lastFlag;

    float* Ls = pool;                 // epilogue overlay

    const int tid = threadIdx.x;
    const int tx  = tid & 3;          // experts tx*16 .. tx*16+15
    const int ty  = tid >> 2;         // rows ty + 64r, r=0..3
    const int row0 = blockIdx.x * BM;

    if (tid < E_DIM) { bsh[tid] = b[tid]; hist[tid] = 0; }
    if (tid == 0) flagCnt = 0;

    unsigned long long acc[4][8];     // sequential fp32 accumulation
#pragma unroll
    for (int r = 0; r < 4; r++)
#pragma unroll
        for (int j = 0; j < 8; j++) acc[r][j] = 0ULL;

    // ---- cp.async staging maps ----
    // x: 512 16B-chunks per tile, 2 per thread
    const float* xsrc[2];
    unsigned xdst[2];
#pragma unroll
    for (int i = 0; i < 2; i++) {
        int qq = tid + i * 256;
        int row = qq >> 1, c = (qq & 1) << 2;
        xsrc[i] = x + (size_t)(row0 + row) * D_DIM + c;
        xdst[i] = (unsigned)((row * XS_STRIDE + c) * 4);
    }
    // w: 128 16B-chunks per tile, threads 0..127
    const int wk = tid >> 4, wg = (tid >> 2) & 3, wi = tid & 3;
    const float* wsrc = Wt + (size_t)wk * E_DIM + wg * 16 + wi * 4;
    const unsigned wdst = (unsigned)((wk * WS_KSTRIDE + wg * 20 + wi * 4) * 4);
    const bool do_w = (tid < 128);

    const unsigned smem0 = (unsigned)__cvta_generic_to_shared(pool);

    // preload tile 0
    cpa16(smem0 + xdst[0], xsrc[0]);
    cpa16(smem0 + xdst[1], xsrc[1]);
    if (do_w) cpa16(smem0 + XBUF_FLOATS * 4 + wdst, wsrc);
    asm volatile("cp.async.commit_group;" ::: "memory");

#pragma unroll 1
    for (int tile = 0; tile < NTILES; tile++) {
        if (tile + 1 < NTILES) {
            const int kb = (tile + 1) * BK;
            const unsigned base = smem0 + ((tile + 1) & 1) * (BUF_FLOATS * 4);
            cpa16(base + xdst[0], xsrc[0] + kb);
            cpa16(base + xdst[1], xsrc[1] + kb);
            if (do_w)
                cpa16(base + XBUF_FLOATS * 4 + wdst, wsrc + (size_t)kb * E_DIM);
            asm volatile("cp.async.commit_group;" ::: "memory");
            asm volatile("cp.async.wait_group 1;" ::: "memory");
        } else {
            asm volatile("cp.async.wait_group 0;" ::: "memory");
        }
        __syncthreads();

        const float* xsb = pool + (tile & 1) * BUF_FLOATS;
        const float* wsb = xsb + XBUF_FLOATS;
        // per k: 4 LDS.128(w, bank-exact) + 4 LDS.32(x, broadcast) + 32 fma2
#pragma unroll
        for (int k = 0; k < BK; k++) {
            const unsigned long long* wr8 =
                (const unsigned long long*)(wsb + k * WS_KSTRIDE + tx * 20);
            ulonglong2 w0 = *(const ulonglong2*)(wr8 + 0);
            ulonglong2 w1 = *(const ulonglong2*)(wr8 + 2);
            ulonglong2 w2 = *(const ulonglong2*)(wr8 + 4);
            ulonglong2 w3 = *(const ulonglong2*)(wr8 + 6);
#pragma unroll
            for (int r = 0; r < 4; r++) {
                float xv = xsb[(r * 64 + ty) * XS_STRIDE + k];
                unsigned long long xd = pack2(xv, xv);
                fma2(acc[r][0], xd, w0.x); fma2(acc[r][1], xd, w0.y);
                fma2(acc[r][2], xd, w1.x); fma2(acc[r][3], xd, w1.y);
                fma2(acc[r][4], xd, w2.x); fma2(acc[r][5], xd, w2.y);
                fma2(acc[r][6], xd, w3.x); fma2(acc[r][7], xd, w3.y);
            }
        }
        __syncthreads();   // all consumers done before buffer reuse
    }

    // ---- spill biased logits: Ls[row][expert], stride 66 ----
#pragma unroll
    for (int r = 0; r < 4; r++) {
        int row = r * 64 + ty;
#pragma unroll
        for (int j = 0; j < 8; j++) {
            int ec = tx * 16 + j * 2;
            float lo = __uint_as_float((unsigned)(acc[r][j] & 0xffffffffULL));
            float hi = __uint_as_float((unsigned)(acc[r][j] >> 32));
            Ls[(size_t)row * LS_STRIDE + ec]     = lo + bsh[ec];
            Ls[(size_t)row * LS_STRIDE + ec + 1] = hi + bsh[ec + 1];
        }
    }
    __syncthreads();

    const float NEG_INF = __int_as_float(0xff800000);
    {
        const int lrow = tid;                  // one row per thread
        const int row = row0 + lrow;
        float* L = Ls + (size_t)lrow * LS_STRIDE;
        float mx = L[0];
#pragma unroll
        for (int e = 1; e < E_DIM; e++) mx = fmaxf(mx, L[e]);
        float s = 0.f;
#pragma unroll
        for (int e = 0; e < E_DIM; e++) s += expf(L[e] - mx);
        float inv = 1.f / s;
        // top-9 by raw logits (strict >, lowest index ties)
        float tv[TOPK + 1]; int ti[TOPK + 1];
        unsigned long long used = 0ULL;
#pragma unroll
        for (int j = 0; j < TOPK + 1; j++) {
            float best = NEG_INF; int bi = 0;
            for (int e = 0; e < E_DIM; e++) {
                float v = L[e];
                if (!((used >> e) & 1ULL) && v > best) { best = v; bi = e; }
            }
            used |= (1ULL << bi);
            tv[j] = best; ti[j] = bi;
        }
        bool close = false;
#pragma unroll
        for (int j = 0; j < TOPK; j++)
            close |= (tv[j] - tv[j + 1]) < GAP_TAU;

        int fidx = -1;
        if (close) {
            fidx = atomicAdd(&flagCnt, 1);
            if (fidx < 64) flagList[fidx] = lrow;
        }
        if (!close || fidx >= 64) {
            float gs = 0.f, gv[TOPK];
#pragma unroll
            for (int j = 0; j < TOPK; j++) {
                float g = expf(tv[j] - mx) * inv;
                gv[j] = g; gs += g;
                atomicAdd(&hist[ti[j]], 1);
            }
            float rn = 1.f / (gs + 1e-8f);
#pragma unroll
            for (int j = 0; j < TOPK; j++) {
                out_idx[(size_t)row * TOPK + j]  = (float)ti[j];
                out_gate[(size_t)row * TOPK + j] = gv[j] * rn;
            }
        }
    }
    __syncthreads();

    // ---- exact refine of flagged rows (chunk-256, matches reference) ----
    {
        const int wid = tid >> 5, lane = tid & 31;
        const int nflag = min(flagCnt, 64);
        for (int fi = wid; fi < nflag; fi += 8) {
            const int lrow = flagList[fi];
            const float* xr = x + (size_t)(row0 + lrow) * D_DIM;
            float tot0 = 0.f, tot1 = 0.f;
#pragma unroll 1
            for (int ch = 0; ch < 4; ch++) {
                float s0 = 0.f, s1 = 0.f;
                const float* xp = xr + ch * 256;
                const float* wp = Wt + (size_t)(ch * 256) * E_DIM;
#pragma unroll 4
                for (int k2 = 0; k2 < 256; k2++) {
                    float xv = __ldg(xp + k2);
                    s0 = fmaf(xv, __ldg(wp + k2 * E_DIM + lane), s0);
                    s1 = fmaf(xv, __ldg(wp + k2 * E_DIM + lane + 32), s1);
                }
                if (ch == 0) { tot0 = s0; tot1 = s1; }
                else         { tot0 += s0; tot1 += s1; }
            }
            float* L = Ls + (size_t)lrow * LS_STRIDE;
            L[lane]      = tot0 + bsh[lane];
            L[lane + 32] = tot1 + bsh[lane + 32];
            __syncwarp();
            if (lane == 0) {
                const int row = row0 + lrow;
                float mx = L[0];
                for (int e = 1; e < E_DIM; e++) mx = fmaxf(mx, L[e]);
                float s = 0.f;
                for (int e = 0; e < E_DIM; e++) s += expf(L[e] - mx);
                float inv = 1.f / s;
                unsigned long long used = 0ULL;
                float gs = 0.f, gv[TOPK]; int gi[TOPK];
                for (int j = 0; j < TOPK; j++) {
                    float best = NEG_INF; int bi = 0;
                    for (int e = 0; e < E_DIM; e++) {
                        float v = L[e];
                        if (!((used >> e) & 1ULL) && v > best) { best = v; bi = e; }
                    }
                    used |= (1ULL << bi);
                    float g = expf(best - mx) * inv;
                    gv[j] = g; gi[j] = bi; gs += g;
                    atomicAdd(&hist[bi], 1);
                }
                float rn = 1.f / (gs + 1e-8f);
                for (int j = 0; j < TOPK; j++) {
                    out_idx[(size_t)row * TOPK + j]  = (float)gi[j];
                    out_gate[(size_t)row * TOPK + j] = gv[j] * rn;
                }
            }
            __syncwarp();
        }
    }
    __syncthreads();
    if (tid < E_DIM) atomicAdd(&g_counts[tid], hist[tid]);

    // ---- fused finisher: last CTA computes EMA-usage variance ----
    __syncthreads();
    if (tid == 0) {
        __threadfence();
        int old = atomicAdd(&g_done, 1);
        lastFlag = (old == (int)gridDim.x - 1);
    }
    __syncthreads();
    if (lastFlag && tid == 0) {
        float u[E_DIM];
        float m = 0.f;
        for (int e = 0; e < E_DIM; e++) {
            int c = atomicExch(&g_counts[e], 0);   // read + reset for replay
            u[e] = 0.95f * eu[e] + 0.05f * ((float)c * invN);
            m += u[e];
        }
        m *= (1.f / E_DIM);
        float v = 0.f;
        for (int e = 0; e < E_DIM; e++) {
            float d = u[e] - m;
            v += d * d;
        }
        *out_var = v * (1.f / (E_DIM - 1));   // ddof=1
        atomicExch(&g_done, 0);               // reset for next replay
    }
}

extern "C" void kernel_launch(void* const* d_in, const int* in_sizes, int n_in,
                              void* d_out, int out_size) {
    const float* x  = (const float*)d_in[0];
    const float* W  = (const float*)d_in[1];
    const float* b  = (const float*)d_in[2];
    const float* eu = (const float*)d_in[3];
    const int N = in_sizes[0] / D_DIM;   // 262144

    float* out      = (float*)d_out;
    float* out_idx  = out;                        // [N,8] indices (as float)
    float* out_gate = out + (size_t)N * TOPK;     // [N,8] gates
    float* out_var  = out + (out_size - 1);       // scalar variance

    static int smem_set = 0;
    if (!smem_set) {
        cudaFuncSetAttribute(gate_kernel,
                             cudaFuncAttributeMaxDynamicSharedMemorySize,
                             SMEM_FLOATS * 4);
        smem_set = 1;
    }

    transpose_w_kernel<<<(E_DIM * D_DIM) / 256, 256>>>(W);
    gate_kernel<<<N / BM, NTHREADS, SMEM_FLOATS * 4>>>(
        x, b, eu, out_idx, out_gate, out_var, 1.f / (float)N);
}

// round 13
// speedup vs baseline: 1.3169x; 1.1039x over previous
#include <cuda_runtime.h>
#include <math.h>

#define D_DIM   1024
#define E_DIM   64
#define TOPK    8
#define BM      256
#define BK      16
#define NTILES  (D_DIM / BK)          // 64
#define NTHREADS 256
#define NSTAGE  3
#define XS_STRIDE 20                  // 16 data + 4 pad (16B-aligned rows)
#define XBUF_FLOATS (BM * XS_STRIDE)            // 5120
#define WS_KSTRIDE 80                 // 4 expert-groups at +20 floats
#define WBUF_FLOATS (BK * WS_KSTRIDE)           // 1280
#define BUF_FLOATS (XBUF_FLOATS + WBUF_FLOATS)  // 6400
#define LS_STRIDE 66
#define SMEM_FLOATS (NSTAGE * BUF_FLOATS)       // 19200 (> 256*66=16896)
#define GAP_TAU 1e-4f

// global scratch (allocation-free per harness rules)
__device__ int   g_counts[E_DIM];
__device__ int   g_done;
__device__ float Wt[D_DIM * E_DIM];   // W transposed: Wt[k][e]

__device__ __forceinline__ unsigned long long pack2(float a, float b) {
    unsigned long long r;
    asm("mov.b64 %0, {%1, %2};" : "=l"(r) : "f"(a), "f"(b));
    return r;
}
__device__ __forceinline__ void fma2(unsigned long long& d,
                                     unsigned long long a,
                                     unsigned long long b) {
    asm("fma.rn.f32x2 %0, %1, %2, %3;" : "=l"(d) : "l"(a), "l"(b), "l"(d));
}
__device__ __forceinline__ void cpa16(unsigned dst, const float* src) {
    asm volatile("cp.async.cg.shared.global [%0], [%1], 16;"
                 :: "r"(dst), "l"(src));
}

__global__ void transpose_w_kernel(const float* __restrict__ W) {
    int idx = blockIdx.x * blockDim.x + threadIdx.x;   // = e*D + k
    int e = idx >> 10, k = idx & (D_DIM - 1);
    Wt[k * E_DIM + e] = W[idx];
}

__global__ __launch_bounds__(NTHREADS, 2)
void gate_kernel(const float* __restrict__ x, const float* __restrict__ b,
                 const float* __restrict__ eu,
                 float* __restrict__ out_idx, float* __restrict__ out_gate,
                 float* __restrict__ out_var, float invN) {
    extern __shared__ __align__(16) float pool[];
    __shared__ float bsh[E_DIM];
    __shared__ int hist[E_DIM];
    __shared__ int flagList[64];
    __shared__ int flagCnt;
    __shared__ int lastFlag;

    float* Ls = pool;                 // epilogue overlay

    const int tid = threadIdx.x;
    const int tx  = tid & 3;          // experts tx*16 .. tx*16+15
    const int ty  = tid >> 2;         // rows ty + 64r, r=0..3
    const int row0 = blockIdx.x * BM;

    if (tid < E_DIM) { bsh[tid] = b[tid]; hist[tid] = 0; }
    if (tid == 0) flagCnt = 0;

    unsigned long long acc[4][8];     // sequential fp32 accumulation
#pragma unroll
    for (int r = 0; r < 4; r++)
#pragma unroll
        for (int j = 0; j < 8; j++) acc[r][j] = 0ULL;

    // ---- cp.async staging maps ----
    // x: 1024 16B-chunks per tile (256 rows x 16 floats), 4 per thread
    const float* xsrc[4];
    unsigned xdst[4];
#pragma unroll
    for (int i = 0; i < 4; i++) {
        int qq = tid + i * 256;                  // 0..1023
        int row = qq >> 2, c = (qq & 3) << 2;    // 4 chunks per row
        xsrc[i] = x + (size_t)(row0 + row) * D_DIM + c;
        xdst[i] = (unsigned)((row * XS_STRIDE + c) * 4);
    }
    // w: 256 16B-chunks per tile (16 krows x 64 experts), 1 per thread
    const int wk = tid >> 4, wseg = tid & 15;
    const float* wsrc = Wt + (size_t)wk * E_DIM + wseg * 4;
    const unsigned wdst = (unsigned)((wk * WS_KSTRIDE
                        + (wseg >> 2) * 20 + (wseg & 3) * 4) * 4);

    const unsigned smem0 = (unsigned)__cvta_generic_to_shared(pool);

    // preload tiles 0 and 1 (groups 0,1)
#pragma unroll
    for (int t = 0; t < 2; t++) {
        const unsigned base = smem0 + t * (BUF_FLOATS * 4);
        const int kb = t * BK;
#pragma unroll
        for (int i = 0; i < 4; i++) cpa16(base + xdst[i], xsrc[i] + kb);
        cpa16(base + XBUF_FLOATS * 4 + wdst, wsrc + (size_t)kb * E_DIM);
        asm volatile("cp.async.commit_group;" ::: "memory");
    }

#pragma unroll 1
    for (int tile = 0; tile < NTILES; tile++) {
        // tile's group must be complete (one group in flight allowed)
        if (tile < NTILES - 1)
            asm volatile("cp.async.wait_group 1;" ::: "memory");
        else
            asm volatile("cp.async.wait_group 0;" ::: "memory");
        __syncthreads();   // all warps: done reading tile-1, tile visible

        // issue tile+2 into ring slot (tile+2)%3 (its last reader was tile-1)
        if (tile + 2 < NTILES) {
            const int kb = (tile + 2) * BK;
            const unsigned base =
                smem0 + ((tile + 2) % NSTAGE) * (BUF_FLOATS * 4);
#pragma unroll
            for (int i = 0; i < 4; i++) cpa16(base + xdst[i], xsrc[i] + kb);
            cpa16(base + XBUF_FLOATS * 4 + wdst, wsrc + (size_t)kb * E_DIM);
            asm volatile("cp.async.commit_group;" ::: "memory");
        }

        const float* xsb = pool + (tile % NSTAGE) * BUF_FLOATS;
        const float* wsb = xsb + XBUF_FLOATS;
        // per k: 4 LDS.128(w, bank-exact) + 4 LDS.32(x, bcast) + 32 fma2
#pragma unroll
        for (int k = 0; k < BK; k++) {
            const unsigned long long* wr8 =
                (const unsigned long long*)(wsb + k * WS_KSTRIDE + tx * 20);
            ulonglong2 w0 = *(const ulonglong2*)(wr8 + 0);
            ulonglong2 w1 = *(const ulonglong2*)(wr8 + 2);
            ulonglong2 w2 = *(const ulonglong2*)(wr8 + 4);
            ulonglong2 w3 = *(const ulonglong2*)(wr8 + 6);
#pragma unroll
            for (int r = 0; r < 4; r++) {
                float xv = xsb[(r * 64 + ty) * XS_STRIDE + k];
                unsigned long long xd = pack2(xv, xv);
                fma2(acc[r][0], xd, w0.x); fma2(acc[r][1], xd, w0.y);
                fma2(acc[r][2], xd, w1.x); fma2(acc[r][3], xd, w1.y);
                fma2(acc[r][4], xd, w2.x); fma2(acc[r][5], xd, w2.y);
                fma2(acc[r][6], xd, w3.x); fma2(acc[r][7], xd, w3.y);
            }
        }
    }
    __syncthreads();

    // ---- spill biased logits: Ls[row][expert], stride 66 ----
#pragma unroll
    for (int r = 0; r < 4; r++) {
        int row = r * 64 + ty;
#pragma unroll
        for (int j = 0; j < 8; j++) {
            int ec = tx * 16 + j * 2;
            float lo = __uint_as_float((unsigned)(acc[r][j] & 0xffffffffULL));
            float hi = __uint_as_float((unsigned)(acc[r][j] >> 32));
            Ls[(size_t)row * LS_STRIDE + ec]     = lo + bsh[ec];
            Ls[(size_t)row * LS_STRIDE + ec + 1] = hi + bsh[ec + 1];
        }
    }
    __syncthreads();

    const float NEG_INF = __int_as_float(0xff800000);
    {
        const int lrow = tid;                  // one row per thread
        const int row = row0 + lrow;
        float* L = Ls + (size_t)lrow * LS_STRIDE;
        float mx = L[0];
#pragma unroll
        for (int e = 1; e < E_DIM; e++) mx = fmaxf(mx, L[e]);
        float s = 0.f;
#pragma unroll
        for (int e = 0; e < E_DIM; e++) s += expf(L[e] - mx);
        float inv = 1.f / s;
        // top-9 by raw logits (strict >, lowest index ties)
        float tv[TOPK + 1]; int ti[TOPK + 1];
        unsigned long long used = 0ULL;
#pragma unroll
        for (int j = 0; j < TOPK + 1; j++) {
            float best = NEG_INF; int bi = 0;
            for (int e = 0; e < E_DIM; e++) {
                float v = L[e];
                if (!((used >> e) & 1ULL) && v > best) { best = v; bi = e; }
            }
            used |= (1ULL << bi);
            tv[j] = best; ti[j] = bi;
        }
        bool close = false;
#pragma unroll
        for (int j = 0; j < TOPK; j++)
            close |= (tv[j] - tv[j + 1]) < GAP_TAU;

        int fidx = -1;
        if (close) {
            fidx = atomicAdd(&flagCnt, 1);
            if (fidx < 64) flagList[fidx] = lrow;
        }
        if (!close || fidx >= 64) {
            float gs = 0.f, gv[TOPK];
#pragma unroll
            for (int j = 0; j < TOPK; j++) {
                float g = expf(tv[j] - mx) * inv;
                gv[j] = g; gs += g;
                atomicAdd(&hist[ti[j]], 1);
            }
            float rn = 1.f / (gs + 1e-8f);
#pragma unroll
            for (int j = 0; j < TOPK; j++) {
                out_idx[(size_t)row * TOPK + j]  = (float)ti[j];
                out_gate[(size_t)row * TOPK + j] = gv[j] * rn;
            }
        }
    }
    __syncthreads();

    // ---- exact refine of flagged rows (chunk-256, matches reference) ----
    {
        const int wid = tid >> 5, lane = tid & 31;
        const int nflag = min(flagCnt, 64);
        for (int fi = wid; fi < nflag; fi += 8) {
            const int lrow = flagList[fi];
            const float* xr = x + (size_t)(row0 + lrow) * D_DIM;
            float tot0 = 0.f, tot1 = 0.f;
#pragma unroll 1
            for (int ch = 0; ch < 4; ch++) {
                float s0 = 0.f, s1 = 0.f;
                const float* xp = xr + ch * 256;
                const float* wp = Wt + (size_t)(ch * 256) * E_DIM;
#pragma unroll 4
                for (int k2 = 0; k2 < 256; k2++) {
                    float xv = __ldg(xp + k2);
                    s0 = fmaf(xv, __ldg(wp + k2 * E_DIM + lane), s0);
                    s1 = fmaf(xv, __ldg(wp + k2 * E_DIM + lane + 32), s1);
                }
                if (ch == 0) { tot0 = s0; tot1 = s1; }
                else         { tot0 += s0; tot1 += s1; }
            }
            float* L = Ls + (size_t)lrow * LS_STRIDE;
            L[lane]      = tot0 + bsh[lane];
            L[lane + 32] = tot1 + bsh[lane + 32];
            __syncwarp();
            if (lane == 0) {
                const int row = row0 + lrow;
                float mx = L[0];
                for (int e = 1; e < E_DIM; e++) mx = fmaxf(mx, L[e]);
                float s = 0.f;
                for (int e = 0; e < E_DIM; e++) s += expf(L[e] - mx);
                float inv = 1.f / s;
                unsigned long long used = 0ULL;
                float gs = 0.f, gv[TOPK]; int gi[TOPK];
                for (int j = 0; j < TOPK; j++) {
                    float best = NEG_INF; int bi = 0;
                    for (int e = 0; e < E_DIM; e++) {
                        float v = L[e];
                        if (!((used >> e) & 1ULL) && v > best) { best = v; bi = e; }
                    }
                    used |= (1ULL << bi);
                    float g = expf(best - mx) * inv;
                    gv[j] = g; gi[j] = bi; gs += g;
                    atomicAdd(&hist[bi], 1);
                }
                float rn = 1.f / (gs + 1e-8f);
                for (int j = 0; j < TOPK; j++) {
                    out_idx[(size_t)row * TOPK + j]  = (float)gi[j];
                    out_gate[(size_t)row * TOPK + j] = gv[j] * rn;
                }
            }
            __syncwarp();
        }
    }
    __syncthreads();
    if (tid < E_DIM) atomicAdd(&g_counts[tid], hist[tid]);

    // ---- fused finisher: last CTA computes EMA-usage variance ----
    __syncthreads();
    if (tid == 0) {
        __threadfence();
        int old = atomicAdd(&g_done, 1);
        lastFlag = (old == (int)gridDim.x - 1);
    }
    __syncthreads();
    if (lastFlag && tid == 0) {
        float u[E_DIM];
        float m = 0.f;
        for (int e = 0; e < E_DIM; e++) {
            int c = atomicExch(&g_counts[e], 0);   // read + reset for replay
            u[e] = 0.95f * eu[e] + 0.05f * ((float)c * invN);
            m += u[e];
        }
        m *= (1.f / E_DIM);
        float v = 0.f;
        for (int e = 0; e < E_DIM; e++) {
            float d = u[e] - m;
            v += d * d;
        }
        *out_var = v * (1.f / (E_DIM - 1));   // ddof=1
        atomicExch(&g_done, 0);               // reset for next replay
    }
}

extern "C" void kernel_launch(void* const* d_in, const int* in_sizes, int n_in,
                              void* d_out, int out_size) {
    const float* x  = (const float*)d_in[0];
    const float* W  = (const float*)d_in[1];
    const float* b  = (const float*)d_in[2];
    const float* eu = (const float*)d_in[3];
    const int N = in_sizes[0] / D_DIM;   // 262144

    float* out      = (float*)d_out;
    float* out_idx  = out;                        // [N,8] indices (as float)
    float* out_gate = out + (size_t)N * TOPK;     // [N,8] gates
    float* out_var  = out + (out_size - 1);       // scalar variance

    static int smem_set = 0;
    if (!smem_set) {
        cudaFuncSetAttribute(gate_kernel,
                             cudaFuncAttributeMaxDynamicSharedMemorySize,
                             SMEM_FLOATS * 4);
        smem_set = 1;
    }

    transpose_w_kernel<<<(E_DIM * D_DIM) / 256, 256>>>(W);
    gate_kernel<<<N / BM, NTHREADS, SMEM_FLOATS * 4>>>(
        x, b, eu, out_idx, out_gate, out_var, 1.f / (float)N);
}

// round 15
// speedup vs baseline: 1.3384x; 1.0163x over previous
#include <cuda_runtime.h>
#include <cuda_bf16.h>
#include <math.h>

#define D_DIM   1024
#define E_DIM   64
#define TOPK    8
#define BM      128
#define CHUNK   64
#define NCHUNK  16
#define NTHREADS 256
#define LS_STRIDE 66
#define GAP_TAU 1e-4f

#define AS_STRIDE 144                 // bytes per A row (64 bf16 + 8 pad)
#define BS_STRIDE 144                 // bytes per B row
#define A_PLANE   (BM * AS_STRIDE)    // 18432
#define B_PLANE   (E_DIM * BS_STRIDE) // 9216
#define A0_OFF 0
#define A1_OFF A_PLANE
#define B0_OFF (2 * A_PLANE)
#define B1_OFF (2 * A_PLANE + B_PLANE)
#define DYN_SMEM (2 * A_PLANE + 2 * B_PLANE)   // 55296

// global scratch (allocation-free per harness rules)
__device__ int   g_counts[E_DIM];
__device__ int   g_done;
__device__ float Wt[D_DIM * E_DIM];              // fp32 W^T for exact refine
__device__ unsigned short WBg[2 * E_DIM * D_DIM];// bf16 split planes [p][e][k]

__device__ __forceinline__ unsigned cvt_bf16x2(float hi, float lo) {
    unsigned r;
    asm("cvt.rn.bf16x2.f32 %0, %1, %2;" : "=r"(r) : "f"(hi), "f"(lo));
    return r;
}
__device__ __forceinline__ void cpa16(unsigned dst, const void* src) {
    asm volatile("cp.async.cg.shared.global [%0], [%1], 16;"
                 :: "r"(dst), "l"(src));
}
__device__ __forceinline__ unsigned smem_u32(const void* p) {
    unsigned a;
    asm("{ .reg .u64 t; cvta.to.shared.u64 t, %1; cvt.u32.u64 %0, t; }"
        : "=r"(a) : "l"(p));
    return a;
}
__device__ __forceinline__ void ldm4(unsigned* r, unsigned addr) {
    asm volatile("ldmatrix.sync.aligned.m8n8.x4.shared.b16 {%0,%1,%2,%3}, [%4];"
        : "=r"(r[0]), "=r"(r[1]), "=r"(r[2]), "=r"(r[3]) : "r"(addr));
}
__device__ __forceinline__ void mma16816(float* d, const unsigned* a,
                                         unsigned b0, unsigned b1) {
    asm volatile(
        "mma.sync.aligned.m16n8k16.row.col.f32.bf16.bf16.f32 "
        "{%0,%1,%2,%3}, {%4,%5,%6,%7}, {%8,%9}, {%0,%1,%2,%3};"
        : "+f"(d[0]), "+f"(d[1]), "+f"(d[2]), "+f"(d[3])
        : "r"(a[0]), "r"(a[1]), "r"(a[2]), "r"(a[3]), "r"(b0), "r"(b1));
}

// One-shot prep: fp32 W^T (refine) + 2 bf16 split planes [p][e][k].
__global__ void prep_kernel(const float* __restrict__ W) {
    int idx = blockIdx.x * blockDim.x + threadIdx.x;   // e*1024 + k
    int e = idx >> 10, k = idx & 1023;
    float v = W[idx];
    Wt[k * E_DIM + e] = v;
    __nv_bfloat16 b0 = __float2bfloat16(v);
    float f0 = __bfloat162float(b0);
    __nv_bfloat16 b1 = __float2bfloat16(v - f0);
    WBg[idx] = __bfloat16_as_ushort(b0);
    WBg[E_DIM * D_DIM + idx] = __bfloat16_as_ushort(b1);
}

__global__ __launch_bounds__(NTHREADS, 2)
void gate_kernel(const float* __restrict__ x, const float* __restrict__ b,
                 const float* __restrict__ eu,
                 float* __restrict__ out_idx, float* __restrict__ out_gate,
                 float* __restrict__ out_var, float invN) {
    extern __shared__ __align__(16) char dyn[];
    __shared__ float bsh[E_DIM];
    __shared__ int hist[E_DIM];
    __shared__ int flagList[64];
    __shared__ int flagCnt;
    __shared__ int lastFlag;

    const int tid = threadIdx.x;
    const int wid = tid >> 5;
    const int lane = tid & 31;
    const int row0 = blockIdx.x * BM;

    if (tid < E_DIM) { bsh[tid] = b[tid]; hist[tid] = 0; }
    if (tid == 0) flagCnt = 0;

    const unsigned sbase = smem_u32(dyn);

    float acc[8][4];                  // 8 n-tiles x 4 f32 (m16n8)
#pragma unroll
    for (int nt = 0; nt < 8; nt++)
#pragma unroll
        for (int q = 0; q < 4; q++) acc[nt][q] = 0.f;

    // x conversion map: thread = (row, half); 32 floats each
    const int arow = tid >> 1, ahalf = tid & 1;
    const float* xrow = x + (size_t)(row0 + arow) * D_DIM + ahalf * 32;
    char* aP0 = dyn + A0_OFF + arow * AS_STRIDE + ahalf * 64;
    char* aP1 = dyn + A1_OFF + arow * AS_STRIDE + ahalf * 64;

    // B cp.async map: 1024 16B chunks (2 planes x 64 rows x 8 segs), 4/thread
    // ldmatrix A/B source addresses (per warp)
    const int mrow0 = wid * 16;
    const unsigned aAddr0 = sbase + A0_OFF + (mrow0 + (lane & 15)) * AS_STRIDE
                          + ((lane >> 4) << 4);
    const unsigned aAddr1 = aAddr0 + A_PLANE;
    const unsigned bGeom  = (((lane >> 4) << 3) + (lane & 7)) * BS_STRIDE
                          + (((lane >> 3) & 1) << 4);
    const unsigned bAddr0 = sbase + B0_OFF + bGeom;
    const unsigned bAddr1 = sbase + B1_OFF + bGeom;

#pragma unroll 1
    for (int c = 0; c < NCHUNK; c++) {
        __syncthreads();   // previous chunk fully consumed
        // ---- B planes via cp.async (global pre-split bf16) ----
#pragma unroll
        for (int t = 0; t < 4; t++) {
            int i = tid + t * 256;                // 0..1023
            int plane = i >> 9, rr = (i >> 3) & 63, seg = i & 7;
            cpa16(sbase + B0_OFF + plane * B_PLANE + rr * BS_STRIDE + seg * 16,
                  WBg + (size_t)plane * (E_DIM * D_DIM) + rr * D_DIM
                      + c * CHUNK + seg * 8);
        }
        asm volatile("cp.async.commit_group;" ::: "memory");
        // ---- A planes: LDG fp32, split to bf16, STS ----
        const float* xp = xrow + c * CHUNK;
#pragma unroll
        for (int j = 0; j < 8; j++) {
            float4 v = __ldg((const float4*)(xp + j * 4));
            unsigned c0 = cvt_bf16x2(v.y, v.x);
            float rx = v.x - __uint_as_float(c0 << 16);
            float ry = v.y - __uint_as_float(c0 & 0xFFFF0000u);
            unsigned c1 = cvt_bf16x2(ry, rx);
            unsigned d0 = cvt_bf16x2(v.w, v.z);
            float rz = v.z - __uint_as_float(d0 << 16);
            float rw = v.w - __uint_as_float(d0 & 0xFFFF0000u);
            unsigned d1 = cvt_bf16x2(rw, rz);
            *(unsigned*)(aP0 + j * 8)     = c0;
            *(unsigned*)(aP0 + j * 8 + 4) = d0;
            *(unsigned*)(aP1 + j * 8)     = c1;
            *(unsigned*)(aP1 + j * 8 + 4) = d1;
        }
        asm volatile("cp.async.wait_group 0;" ::: "memory");
        __syncthreads();
        // ---- 4 k16-steps of HMMA ----
#pragma unroll
        for (int ks = 0; ks < 4; ks++) {
            const unsigned ko = ks * 32;          // k0*2 bytes
            unsigned af0[4], af1[4];
            ldm4(af0, aAddr0 + ko);
            ldm4(af1, aAddr1 + ko);
#pragma unroll
            for (int p = 0; p < 4; p++) {
                unsigned b0f[4], b1f[4];
                ldm4(b0f, bAddr0 + p * (16 * BS_STRIDE) + ko);
                ldm4(b1f, bAddr1 + p * (16 * BS_STRIDE) + ko);
#pragma unroll
                for (int t = 0; t < 2; t++) {
                    mma16816(acc[2 * p + t], af0, b0f[2 * t], b0f[2 * t + 1]);
                    mma16816(acc[2 * p + t], af0, b1f[2 * t], b1f[2 * t + 1]);
                    mma16816(acc[2 * p + t], af1, b0f[2 * t], b0f[2 * t + 1]);
                }
            }
        }
    }
    __syncthreads();   // tiles dead -> Ls overlay

    // ---- spill biased logits: Ls[row][expert], stride 66 ----
    float* Ls = (float*)dyn;
    {
        const int gr = lane >> 2, gc = (lane & 3) * 2;
#pragma unroll
        for (int nt = 0; nt < 8; nt++) {
            int col = nt * 8 + gc;
            int r0 = mrow0 + gr, r1 = mrow0 + gr + 8;
            Ls[(size_t)r0 * LS_STRIDE + col]     = acc[nt][0] + bsh[col];
            Ls[(size_t)r0 * LS_STRIDE + col + 1] = acc[nt][1] + bsh[col + 1];
            Ls[(size_t)r1 * LS_STRIDE + col]     = acc[nt][2] + bsh[col];
            Ls[(size_t)r1 * LS_STRIDE + col + 1] = acc[nt][3] + bsh[col + 1];
        }
    }
    __syncthreads();

    const float NEG_INF = __int_as_float(0xff800000);
    if (tid < BM) {
        const int lrow = tid;
        const int row = row0 + lrow;
        float* L = Ls + (size_t)lrow * LS_STRIDE;
        float mx = L[0];
#pragma unroll
        for (int e = 1; e < E_DIM; e++) mx = fmaxf(mx, L[e]);
        float s = 0.f;
#pragma unroll
        for (int e = 0; e < E_DIM; e++) s += expf(L[e] - mx);
        float inv = 1.f / s;
        // top-9 by raw logits (strict >, lowest index ties)
        float tv[TOPK + 1]; int ti[TOPK + 1];
        unsigned long long used = 0ULL;
#pragma unroll
        for (int j = 0; j < TOPK + 1; j++) {
            float best = NEG_INF; int bi = 0;
            for (int e = 0; e < E_DIM; e++) {
                float v = L[e];
                if (!((used >> e) & 1ULL) && v > best) { best = v; bi = e; }
            }
            used |= (1ULL << bi);
            tv[j] = best; ti[j] = bi;
        }
        bool close = false;
#pragma unroll
        for (int j = 0; j < TOPK; j++)
            close |= (tv[j] - tv[j + 1]) < GAP_TAU;

        int fidx = -1;
        if (close) {
            fidx = atomicAdd(&flagCnt, 1);
            if (fidx < 64) flagList[fidx] = lrow;
        }
        if (!close || fidx >= 64) {
            float gs = 0.f, gv[TOPK];
#pragma unroll
            for (int j = 0; j < TOPK; j++) {
                float g = expf(tv[j] - mx) * inv;
                gv[j] = g; gs += g;
                atomicAdd(&hist[ti[j]], 1);
            }
            float rn = 1.f / (gs + 1e-8f);
#pragma unroll
            for (int j = 0; j < TOPK; j++) {
                out_idx[(size_t)row * TOPK + j]  = (float)ti[j];
                out_gate[(size_t)row * TOPK + j] = gv[j] * rn;
            }
        }
    }
    __syncthreads();

    // ---- exact refine of flagged rows (chunk-256 fp32, ref-matching) ----
    {
        const int nflag = min(flagCnt, 64);
        for (int fi = wid; fi < nflag; fi += 8) {
            const int lrow = flagList[fi];
            const float* xr = x + (size_t)(row0 + lrow) * D_DIM;
            float tot0 = 0.f, tot1 = 0.f;
#pragma unroll 1
            for (int ch = 0; ch < 4; ch++) {
                float s0 = 0.f, s1 = 0.f;
                const float* xp = xr + ch * 256;
                const float* wp = Wt + (size_t)(ch * 256) * E_DIM;
#pragma unroll 4
                for (int k2 = 0; k2 < 256; k2++) {
                    float xv = __ldg(xp + k2);
                    s0 = fmaf(xv, __ldg(wp + k2 * E_DIM + lane), s0);
                    s1 = fmaf(xv, __ldg(wp + k2 * E_DIM + lane + 32), s1);
                }
                if (ch == 0) { tot0 = s0; tot1 = s1; }
                else         { tot0 += s0; tot1 += s1; }
            }
            float* L = Ls + (size_t)lrow * LS_STRIDE;
            L[lane]      = tot0 + bsh[lane];
            L[lane + 32] = tot1 + bsh[lane + 32];
            __syncwarp();
            if (lane == 0) {
                const int row = row0 + lrow;
                float mx = L[0];
                for (int e = 1; e < E_DIM; e++) mx = fmaxf(mx, L[e]);
                float s = 0.f;
                for (int e = 0; e < E_DIM; e++) s += expf(L[e] - mx);
                float inv = 1.f / s;
                unsigned long long used = 0ULL;
                float gs = 0.f, gv[TOPK]; int gi[TOPK];
                for (int j = 0; j < TOPK; j++) {
                    float best = NEG_INF; int bi = 0;
                    for (int e = 0; e < E_DIM; e++) {
                        float v = L[e];
                        if (!((used >> e) & 1ULL) && v > best) { best = v; bi = e; }
                    }
                    used |= (1ULL << bi);
                    float g = expf(best - mx) * inv;
                    gv[j] = g; gi[j] = bi; gs += g;
                    atomicAdd(&hist[bi], 1);
                }
                float rn = 1.f / (gs + 1e-8f);
                for (int j = 0; j < TOPK; j++) {
                    out_idx[(size_t)row * TOPK + j]  = (float)gi[j];
                    out_gate[(size_t)row * TOPK + j] = gv[j] * rn;
                }
            }
            __syncwarp();
        }
    }
    __syncthreads();
    if (tid < E_DIM) atomicAdd(&g_counts[tid], hist[tid]);

    // ---- fused finisher: last CTA computes EMA-usage variance ----
    __syncthreads();
    if (tid == 0) {
        __threadfence();
        int old = atomicAdd(&g_done, 1);
        lastFlag = (old == (int)gridDim.x - 1);
    }
    __syncthreads();
    if (lastFlag && tid == 0) {
        float u[E_DIM];
        float m = 0.f;
        for (int e = 0; e < E_DIM; e++) {
            int c = atomicExch(&g_counts[e], 0);   // read + reset for replay
            u[e] = 0.95f * eu[e] + 0.05f * ((float)c * invN);
            m += u[e];
        }
        m *= (1.f / E_DIM);
        float v = 0.f;
        for (int e = 0; e < E_DIM; e++) {
            float d = u[e] - m;
            v += d * d;
        }
        *out_var = v * (1.f / (E_DIM - 1));   // ddof=1
        atomicExch(&g_done, 0);               // reset for next replay
    }
}

extern "C" void kernel_launch(void* const* d_in, const int* in_sizes, int n_in,
                              void* d_out, int out_size) {
    const float* x  = (const float*)d_in[0];
    const float* W  = (const float*)d_in[1];
    const float* b  = (const float*)d_in[2];
    const float* eu = (const float*)d_in[3];
    const int N = in_sizes[0] / D_DIM;   // 262144

    float* out      = (float*)d_out;
    float* out_idx  = out;                        // [N,8] indices (as float)
    float* out_gate = out + (size_t)N * TOPK;     // [N,8] gates
    float* out_var  = out + (out_size - 1);       // scalar variance

    static int smem_set = 0;
    if (!smem_set) {
        cudaFuncSetAttribute(gate_kernel,
                             cudaFuncAttributeMaxDynamicSharedMemorySize,
                             DYN_SMEM);
        smem_set = 1;
    }

    prep_kernel<<<(E_DIM * D_DIM) / 256, 256>>>(W);
    gate_kernel<<<N / BM, NTHREADS, DYN_SMEM>>>(
        x, b, eu, out_idx, out_gate, out_var, 1.f / (float)N);
}

// round 16
// speedup vs baseline: 1.8511x; 1.3830x over previous
#include <cuda_runtime.h>
#include <cuda_bf16.h>
#include <math.h>

#define D_DIM   1024
#define E_DIM   64
#define TOPK    8
#define BM      128
#define CHUNK   64
#define NCHUNK  16
#define NSTAGE  3
#define NTHREADS 256
#define LS_STRIDE 66
#define GAP_TAU 1e-4f

#define BS_STRIDE 144                 // bytes per B row (64 bf16 + 8 pad)
#define B_PLANE   (E_DIM * BS_STRIDE) // 9216
#define STAGE_BYTES (2 * B_PLANE)     // 18432
#define DYN_SMEM (NSTAGE * STAGE_BYTES)   // 55296 (> 128*66*4 = 33792 Ls)

// global scratch (allocation-free per harness rules)
__device__ int   g_counts[E_DIM];
__device__ int   g_done;
__device__ float Wt[D_DIM * E_DIM];              // fp32 W^T for exact refine
__device__ unsigned short WBg[2 * E_DIM * D_DIM];// bf16 split planes [p][e][k]

__device__ __forceinline__ unsigned cvt_bf16x2(float hi, float lo) {
    unsigned r;
    asm("cvt.rn.bf16x2.f32 %0, %1, %2;" : "=r"(r) : "f"(hi), "f"(lo));
    return r;
}
__device__ __forceinline__ void cpa16(unsigned dst, const void* src) {
    asm volatile("cp.async.cg.shared.global [%0], [%1], 16;"
                 :: "r"(dst), "l"(src));
}
__device__ __forceinline__ unsigned smem_u32(const void* p) {
    unsigned a;
    asm("{ .reg .u64 t; cvta.to.shared.u64 t, %1; cvt.u32.u64 %0, t; }"
        : "=r"(a) : "l"(p));
    return a;
}
__device__ __forceinline__ void ldm4(unsigned* r, unsigned addr) {
    asm volatile("ldmatrix.sync.aligned.m8n8.x4.shared.b16 {%0,%1,%2,%3}, [%4];"
        : "=r"(r[0]), "=r"(r[1]), "=r"(r[2]), "=r"(r[3]) : "r"(addr));
}
__device__ __forceinline__ void mma16816(float* d, const unsigned* a,
                                         unsigned b0, unsigned b1) {
    asm volatile(
        "mma.sync.aligned.m16n8k16.row.col.f32.bf16.bf16.f32 "
        "{%0,%1,%2,%3}, {%4,%5,%6,%7}, {%8,%9}, {%0,%1,%2,%3};"
        : "+f"(d[0]), "+f"(d[1]), "+f"(d[2]), "+f"(d[3])
        : "r"(a[0]), "r"(a[1]), "r"(a[2]), "r"(a[3]), "r"(b0), "r"(b1));
}
// split one fp32 pair into bf16x2 plane0 + residual plane1
__device__ __forceinline__ void split2(float2 v, unsigned& p0, unsigned& p1) {
    p0 = cvt_bf16x2(v.y, v.x);
    float rx = v.x - __uint_as_float(p0 << 16);
    float ry = v.y - __uint_as_float(p0 & 0xFFFF0000u);
    p1 = cvt_bf16x2(ry, rx);
}

// One-shot prep: fp32 W^T (refine) + 2 bf16 split planes [p][e][k].
__global__ void prep_kernel(const float* __restrict__ W) {
    int idx = blockIdx.x * blockDim.x + threadIdx.x;   // e*1024 + k
    int e = idx >> 10, k = idx & 1023;
    float v = W[idx];
    Wt[k * E_DIM + e] = v;
    __nv_bfloat16 b0 = __float2bfloat16(v);
    float f0 = __bfloat162float(b0);
    __nv_bfloat16 b1 = __float2bfloat16(v - f0);
    WBg[idx] = __bfloat16_as_ushort(b0);
    WBg[E_DIM * D_DIM + idx] = __bfloat16_as_ushort(b1);
}

__global__ __launch_bounds__(NTHREADS, 2)
void gate_kernel(const float* __restrict__ x, const float* __restrict__ b,
                 const float* __restrict__ eu,
                 float* __restrict__ out_idx, float* __restrict__ out_gate,
                 float* __restrict__ out_var, float invN) {
    extern __shared__ __align__(16) char dyn[];
    __shared__ float bsh[E_DIM];
    __shared__ int hist[E_DIM];
    __shared__ int flagList[64];
    __shared__ int flagCnt;
    __shared__ int lastFlag;

    const int tid = threadIdx.x;
    const int wid = tid >> 5;
    const int lane = tid & 31;
    const int row0 = blockIdx.x * BM;

    if (tid < E_DIM) { bsh[tid] = b[tid]; hist[tid] = 0; }
    if (tid == 0) flagCnt = 0;

    const unsigned sbase = smem_u32(dyn);

    float acc[8][4];                  // 8 n-tiles x 4 f32 (m16n8)
#pragma unroll
    for (int nt = 0; nt < 8; nt++)
#pragma unroll
        for (int q = 0; q < 4; q++) acc[nt][q] = 0.f;

    // A fragments straight from gmem: lane holds rows mrow0+gid(+8), cols 2t
    const int mrow0 = wid * 16;
    const int gid = lane >> 2, tid2 = (lane & 3) * 2;
    const float* xA = x + (size_t)(row0 + mrow0 + gid) * D_DIM + tid2;

    // B cp.async map: 1024 16B chunks (2 planes x 64 rows x 8 segs), 4/thread
    // B ldmatrix geometry (per warp, verified in R15)
    const unsigned bGeom = (((lane >> 4) << 3) + (lane & 7)) * BS_STRIDE
                         + (((lane >> 3) & 1) << 4);

    // preload B stages 0,1
#pragma unroll
    for (int s = 0; s < 2; s++) {
#pragma unroll
        for (int t = 0; t < 4; t++) {
            int i = tid + t * 256;
            int plane = i >> 9, rr = (i >> 3) & 63, seg = i & 7;
            cpa16(sbase + s * STAGE_BYTES + plane * B_PLANE + rr * BS_STRIDE + seg * 16,
                  WBg + (size_t)plane * (E_DIM * D_DIM) + rr * D_DIM
                      + s * CHUNK + seg * 8);
        }
        asm volatile("cp.async.commit_group;" ::: "memory");
    }

#pragma unroll 1
    for (int c = 0; c < NCHUNK; c++) {
        // ---- x loads for this chunk (independent of B barrier) ----
        const float* xk = xA + c * CHUNK;
        float2 xv[4][4];
#pragma unroll
        for (int ks = 0; ks < 4; ks++) {
            const int kb = ks * 16;
            xv[ks][0] = *(const float2*)(xk + kb);
            xv[ks][1] = *(const float2*)(xk + (size_t)8 * D_DIM + kb);
            xv[ks][2] = *(const float2*)(xk + kb + 8);
            xv[ks][3] = *(const float2*)(xk + (size_t)8 * D_DIM + kb + 8);
        }
        // ---- B stage c ready ----
        if (c + 1 < NCHUNK)
            asm volatile("cp.async.wait_group 1;" ::: "memory");
        else
            asm volatile("cp.async.wait_group 0;" ::: "memory");
        __syncthreads();
        // issue stage c+2 (its buffer's last reader finished before this barrier)
        if (c + 2 < NCHUNK) {
            const unsigned sb = sbase + ((c + 2) % NSTAGE) * STAGE_BYTES;
#pragma unroll
            for (int t = 0; t < 4; t++) {
                int i = tid + t * 256;
                int plane = i >> 9, rr = (i >> 3) & 63, seg = i & 7;
                cpa16(sb + plane * B_PLANE + rr * BS_STRIDE + seg * 16,
                      WBg + (size_t)plane * (E_DIM * D_DIM) + rr * D_DIM
                          + (c + 2) * CHUNK + seg * 8);
            }
            asm volatile("cp.async.commit_group;" ::: "memory");
        }
        // ---- compute: 4 k16-steps, A from regs, B via ldmatrix ----
        const unsigned bAddr0 = sbase + (c % NSTAGE) * STAGE_BYTES + bGeom;
        const unsigned bAddr1 = bAddr0 + B_PLANE;
#pragma unroll
        for (int ks = 0; ks < 4; ks++) {
            unsigned af0[4], af1[4];
#pragma unroll
            for (int i = 0; i < 4; i++) split2(xv[ks][i], af0[i], af1[i]);
            const unsigned ko = ks * 32;
#pragma unroll
            for (int p = 0; p < 4; p++) {
                unsigned b0f[4], b1f[4];
                ldm4(b0f, bAddr0 + p * (16 * BS_STRIDE) + ko);
                ldm4(b1f, bAddr1 + p * (16 * BS_STRIDE) + ko);
#pragma unroll
                for (int t = 0; t < 2; t++) {
                    mma16816(acc[2 * p + t], af0, b0f[2 * t], b0f[2 * t + 1]);
                    mma16816(acc[2 * p + t], af0, b1f[2 * t], b1f[2 * t + 1]);
                    mma16816(acc[2 * p + t], af1, b0f[2 * t], b0f[2 * t + 1]);
                }
            }
        }
    }
    __syncthreads();   // B ring dead -> Ls overlay

    // ---- spill biased logits: Ls[row][expert], stride 66 ----
    float* Ls = (float*)dyn;
    {
        const int gr = lane >> 2, gc = (lane & 3) * 2;
#pragma unroll
        for (int nt = 0; nt < 8; nt++) {
            int col = nt * 8 + gc;
            int r0 = mrow0 + gr, r1 = mrow0 + gr + 8;
            Ls[(size_t)r0 * LS_STRIDE + col]     = acc[nt][0] + bsh[col];
            Ls[(size_t)r0 * LS_STRIDE + col + 1] = acc[nt][1] + bsh[col + 1];
            Ls[(size_t)r1 * LS_STRIDE + col]     = acc[nt][2] + bsh[col];
            Ls[(size_t)r1 * LS_STRIDE + col + 1] = acc[nt][3] + bsh[col + 1];
        }
    }
    __syncthreads();

    const float NEG_INF = __int_as_float(0xff800000);
    if (tid < BM) {
        const int lrow = tid;
        const int row = row0 + lrow;
        float* L = Ls + (size_t)lrow * LS_STRIDE;
        float mx = L[0];
#pragma unroll
        for (int e = 1; e < E_DIM; e++) mx = fmaxf(mx, L[e]);
        float s = 0.f;
#pragma unroll
        for (int e = 0; e < E_DIM; e++) s += expf(L[e] - mx);
        float inv = 1.f / s;
        // top-9 by raw logits (strict >, lowest index ties)
        float tv[TOPK + 1]; int ti[TOPK + 1];
        unsigned long long used = 0ULL;
#pragma unroll
        for (int j = 0; j < TOPK + 1; j++) {
            float best = NEG_INF; int bi = 0;
            for (int e = 0; e < E_DIM; e++) {
                float v = L[e];
                if (!((used >> e) & 1ULL) && v > best) { best = v; bi = e; }
            }
            used |= (1ULL << bi);
            tv[j] = best; ti[j] = bi;
        }
        bool close = false;
#pragma unroll
        for (int j = 0; j < TOPK; j++)
            close |= (tv[j] - tv[j + 1]) < GAP_TAU;

        int fidx = -1;
        if (close) {
            fidx = atomicAdd(&flagCnt, 1);
            if (fidx < 64) flagList[fidx] = lrow;
        }
        if (!close || fidx >= 64) {
            float gs = 0.f, gv[TOPK];
#pragma unroll
            for (int j = 0; j < TOPK; j++) {
                float g = expf(tv[j] - mx) * inv;
                gv[j] = g; gs += g;
                atomicAdd(&hist[ti[j]], 1);
            }
            float rn = 1.f / (gs + 1e-8f);
#pragma unroll
            for (int j = 0; j < TOPK; j++) {
                out_idx[(size_t)row * TOPK + j]  = (float)ti[j];
                out_gate[(size_t)row * TOPK + j] = gv[j] * rn;
            }
        }
    }
    __syncthreads();

    // ---- exact refine of flagged rows (chunk-256 fp32, ref-matching) ----
    {
        const int nflag = min(flagCnt, 64);
        for (int fi = wid; fi < nflag; fi += 8) {
            const int lrow = flagList[fi];
            const float* xr = x + (size_t)(row0 + lrow) * D_DIM;
            float tot0 = 0.f, tot1 = 0.f;
#pragma unroll 1
            for (int ch = 0; ch < 4; ch++) {
                float s0 = 0.f, s1 = 0.f;
                const float* xp = xr + ch * 256;
                const float* wp = Wt + (size_t)(ch * 256) * E_DIM;
#pragma unroll 4
                for (int k2 = 0; k2 < 256; k2++) {
                    float xv = __ldg(xp + k2);
                    s0 = fmaf(xv, __ldg(wp + k2 * E_DIM + lane), s0);
                    s1 = fmaf(xv, __ldg(wp + k2 * E_DIM + lane + 32), s1);
                }
                if (ch == 0) { tot0 = s0; tot1 = s1; }
                else         { tot0 += s0; tot1 += s1; }
            }
            float* L = Ls + (size_t)lrow * LS_STRIDE;
            L[lane]      = tot0 + bsh[lane];
            L[lane + 32] = tot1 + bsh[lane + 32];
            __syncwarp();
            if (lane == 0) {
                const int row = row0 + lrow;
                float mx = L[0];
                for (int e = 1; e < E_DIM; e++) mx = fmaxf(mx, L[e]);
                float s = 0.f;
                for (int e = 0; e < E_DIM; e++) s += expf(L[e] - mx);
                float inv = 1.f / s;
                unsigned long long used = 0ULL;
                float gs = 0.f, gv[TOPK]; int gi[TOPK];
                for (int j = 0; j < TOPK; j++) {
                    float best = NEG_INF; int bi = 0;
                    for (int e = 0; e < E_DIM; e++) {
                        float v = L[e];
                        if (!((used >> e) & 1ULL) && v > best) { best = v; bi = e; }
                    }
                    used |= (1ULL << bi);
                    float g = expf(best - mx) * inv;
                    gv[j] = g; gi[j] = bi; gs += g;
                    atomicAdd(&hist[bi], 1);
                }
                float rn = 1.f / (gs + 1e-8f);
                for (int j = 0; j < TOPK; j++) {
                    out_idx[(size_t)row * TOPK + j]  = (float)gi[j];
                    out_gate[(size_t)row * TOPK + j] = gv[j] * rn;
                }
            }
            __syncwarp();
        }
    }
    __syncthreads();
    if (tid < E_DIM) atomicAdd(&g_counts[tid], hist[tid]);

    // ---- fused finisher: last CTA computes EMA-usage variance ----
    __syncthreads();
    if (tid == 0) {
        __threadfence();
        int old = atomicAdd(&g_done, 1);
        lastFlag = (old == (int)gridDim.x - 1);
    }
    __syncthreads();
    if (lastFlag && tid == 0) {
        float u[E_DIM];
        float m = 0.f;
        for (int e = 0; e < E_DIM; e++) {
            int c = atomicExch(&g_counts[e], 0);   // read + reset for replay
            u[e] = 0.95f * eu[e] + 0.05f * ((float)c * invN);
            m += u[e];
        }
        m *= (1.f / E_DIM);
        float v = 0.f;
        for (int e = 0; e < E_DIM; e++) {
            float d = u[e] - m;
            v += d * d;
        }
        *out_var = v * (1.f / (E_DIM - 1));   // ddof=1
        atomicExch(&g_done, 0);               // reset for next replay
    }
}

extern "C" void kernel_launch(void* const* d_in, const int* in_sizes, int n_in,
                              void* d_out, int out_size) {
    const float* x  = (const float*)d_in[0];
    const float* W  = (const float*)d_in[1];
    const float* b  = (const float*)d_in[2];
    const float* eu = (const float*)d_in[3];
    const int N = in_sizes[0] / D_DIM;   // 262144

    float* out      = (float*)d_out;
    float* out_idx  = out;                        // [N,8] indices (as float)
    float* out_gate = out + (size_t)N * TOPK;     // [N,8] gates
    float* out_var  = out + (out_size - 1);       // scalar variance

    static int smem_set = 0;
    if (!smem_set) {
        cudaFuncSetAttribute(gate_kernel,
                             cudaFuncAttributeMaxDynamicSharedMemorySize,
                             DYN_SMEM);
        smem_set = 1;
    }

    prep_kernel<<<(E_DIM * D_DIM) / 256, 256>>>(W);
    gate_kernel<<<N / BM, NTHREADS, DYN_SMEM>>>(
        x, b, eu, out_idx, out_gate, out_var, 1.f / (float)N);
}

// round 17
// speedup vs baseline: 1.8893x; 1.0206x over previous
#include <cuda_runtime.h>
#include <cuda_bf16.h>
#include <math.h>

#define D_DIM   1024
#define E_DIM   64
#define TOPK    8
#define BM      128
#define CHUNK   64
#define NCHUNK  16
#define NSTAGE  3
#define NTHREADS 256
#define LS_STRIDE 66
#define GAP_TAU 1e-4f

#define BS_STRIDE 144                 // bytes per B row (64 bf16 + 8 pad)
#define B_PLANE   (E_DIM * BS_STRIDE) // 9216
#define STAGE_BYTES (2 * B_PLANE)     // 18432
#define DYN_SMEM (NSTAGE * STAGE_BYTES)   // 55296 (> 128*66*4 = 33792 Ls)

// global scratch (allocation-free per harness rules)
__device__ int   g_counts[E_DIM];
__device__ int   g_done;
__device__ float Wt[D_DIM * E_DIM];              // fp32 W^T for exact refine
__device__ unsigned short WBg[2 * E_DIM * D_DIM];// bf16 split planes [p][e][k]

__device__ __forceinline__ unsigned cvt_bf16x2(float hi, float lo) {
    unsigned r;
    asm("cvt.rn.bf16x2.f32 %0, %1, %2;" : "=r"(r) : "f"(hi), "f"(lo));
    return r;
}
__device__ __forceinline__ void cpa16(unsigned dst, const void* src) {
    asm volatile("cp.async.cg.shared.global [%0], [%1], 16;"
                 :: "r"(dst), "l"(src));
}
__device__ __forceinline__ unsigned smem_u32(const void* p) {
    unsigned a;
    asm("{ .reg .u64 t; cvta.to.shared.u64 t, %1; cvt.u32.u64 %0, t; }"
        : "=r"(a) : "l"(p));
    return a;
}
__device__ __forceinline__ void ldm4(unsigned* r, unsigned addr) {
    asm volatile("ldmatrix.sync.aligned.m8n8.x4.shared.b16 {%0,%1,%2,%3}, [%4];"
        : "=r"(r[0]), "=r"(r[1]), "=r"(r[2]), "=r"(r[3]) : "r"(addr));
}
__device__ __forceinline__ void mma16816(float* d, const unsigned* a,
                                         unsigned b0, unsigned b1) {
    asm volatile(
        "mma.sync.aligned.m16n8k16.row.col.f32.bf16.bf16.f32 "
        "{%0,%1,%2,%3}, {%4,%5,%6,%7}, {%8,%9}, {%0,%1,%2,%3};"
        : "+f"(d[0]), "+f"(d[1]), "+f"(d[2]), "+f"(d[3])
        : "r"(a[0]), "r"(a[1]), "r"(a[2]), "r"(a[3]), "r"(b0), "r"(b1));
}
// split one fp32 pair into bf16x2 plane0 + residual plane1
__device__ __forceinline__ void split2(float2 v, unsigned& p0, unsigned& p1) {
    p0 = cvt_bf16x2(v.y, v.x);
    float rx = v.x - __uint_as_float(p0 << 16);
    float ry = v.y - __uint_as_float(p0 & 0xFFFF0000u);
    p1 = cvt_bf16x2(ry, rx);
}

// One-shot prep: fp32 W^T (refine) + 2 bf16 split planes [p][e][k].
__global__ void prep_kernel(const float* __restrict__ W) {
    int idx = blockIdx.x * blockDim.x + threadIdx.x;   // e*1024 + k
    int e = idx >> 10, k = idx & 1023;
    float v = W[idx];
    Wt[k * E_DIM + e] = v;
    __nv_bfloat16 b0 = __float2bfloat16(v);
    float f0 = __bfloat162float(b0);
    __nv_bfloat16 b1 = __float2bfloat16(v - f0);
    WBg[idx] = __bfloat16_as_ushort(b0);
    WBg[E_DIM * D_DIM + idx] = __bfloat16_as_ushort(b1);
}

__global__ __launch_bounds__(NTHREADS, 2)
void gate_kernel(const float* __restrict__ x, const float* __restrict__ b,
                 const float* __restrict__ eu,
                 float* __restrict__ out_idx, float* __restrict__ out_gate,
                 float* __restrict__ out_var, float invN) {
    extern __shared__ __align__(16) char dyn[];
    __shared__ float bsh[E_DIM];
    __shared__ int hist[E_DIM];
    __shared__ int flagList[64];
    __shared__ int flagCnt;
    __shared__ int lastFlag;

    const int tid = threadIdx.x;
    const int wid = tid >> 5;
    const int lane = tid & 31;
    const int row0 = blockIdx.x * BM;

    if (tid < E_DIM) { bsh[tid] = b[tid]; hist[tid] = 0; }
    if (tid == 0) flagCnt = 0;

    const unsigned sbase = smem_u32(dyn);

    float acc[8][4];                  // 8 n-tiles x 4 f32 (m16n8)
#pragma unroll
    for (int nt = 0; nt < 8; nt++)
#pragma unroll
        for (int q = 0; q < 4; q++) acc[nt][q] = 0.f;

    // A fragments straight from gmem: lane holds rows mrow0+gid(+8), cols 2t
    const int mrow0 = wid * 16;
    const int gid = lane >> 2, tid2 = (lane & 3) * 2;
    const float* xA = x + (size_t)(row0 + mrow0 + gid) * D_DIM + tid2;

    // B ldmatrix geometry (per warp, verified in R15/R16)
    const unsigned bGeom = (((lane >> 4) << 3) + (lane & 7)) * BS_STRIDE
                         + (((lane >> 3) & 1) << 4);

    // preload B stages 0,1
#pragma unroll
    for (int s = 0; s < 2; s++) {
#pragma unroll
        for (int t = 0; t < 4; t++) {
            int i = tid + t * 256;
            int plane = i >> 9, rr = (i >> 3) & 63, seg = i & 7;
            cpa16(sbase + s * STAGE_BYTES + plane * B_PLANE + rr * BS_STRIDE + seg * 16,
                  WBg + (size_t)plane * (E_DIM * D_DIM) + rr * D_DIM
                      + s * CHUNK + seg * 8);
        }
        asm volatile("cp.async.commit_group;" ::: "memory");
    }

    // preload x for chunk 0 (software pipeline, 1-chunk lookahead)
    float2 xv[4][4];
#pragma unroll
    for (int ks = 0; ks < 4; ks++) {
        const int kb = ks * 16;
        xv[ks][0] = *(const float2*)(xA + kb);
        xv[ks][1] = *(const float2*)(xA + (size_t)8 * D_DIM + kb);
        xv[ks][2] = *(const float2*)(xA + kb + 8);
        xv[ks][3] = *(const float2*)(xA + (size_t)8 * D_DIM + kb + 8);
    }

#pragma unroll 1
    for (int c = 0; c < NCHUNK; c++) {
        // ---- B stage c ready ----
        if (c + 1 < NCHUNK)
            asm volatile("cp.async.wait_group 1;" ::: "memory");
        else
            asm volatile("cp.async.wait_group 0;" ::: "memory");
        __syncthreads();
        // issue stage c+2 (its buffer's last reader finished before this barrier)
        if (c + 2 < NCHUNK) {
            const unsigned sb = sbase + ((c + 2) % NSTAGE) * STAGE_BYTES;
#pragma unroll
            for (int t = 0; t < 4; t++) {
                int i = tid + t * 256;
                int plane = i >> 9, rr = (i >> 3) & 63, seg = i & 7;
                cpa16(sb + plane * B_PLANE + rr * BS_STRIDE + seg * 16,
                      WBg + (size_t)plane * (E_DIM * D_DIM) + rr * D_DIM
                          + (c + 2) * CHUNK + seg * 8);
            }
            asm volatile("cp.async.commit_group;" ::: "memory");
        }
        // ---- compute: 4 k16-steps; A from pipelined regs, B via ldmatrix ----
        const unsigned bAddr0 = sbase + (c % NSTAGE) * STAGE_BYTES + bGeom;
        const unsigned bAddr1 = bAddr0 + B_PLANE;
        const float* xn = xA + (c + 1) * CHUNK;   // next chunk's x
        const bool more = (c + 1 < NCHUNK);
#pragma unroll
        for (int ks = 0; ks < 4; ks++) {
            unsigned af0[4], af1[4];
#pragma unroll
            for (int i = 0; i < 4; i++) split2(xv[ks][i], af0[i], af1[i]);
            // refill this ks-slot from chunk c+1 (consumed above; long
            // load-use distance = rest of this chunk + next B-wait)
            if (more) {
                const int kb = ks * 16;
                xv[ks][0] = *(const float2*)(xn + kb);
                xv[ks][1] = *(const float2*)(xn + (size_t)8 * D_DIM + kb);
                xv[ks][2] = *(const float2*)(xn + kb + 8);
                xv[ks][3] = *(const float2*)(xn + (size_t)8 * D_DIM + kb + 8);
            }
            const unsigned ko = ks * 32;
#pragma unroll
            for (int p = 0; p < 4; p++) {
                unsigned b0f[4], b1f[4];
                ldm4(b0f, bAddr0 + p * (16 * BS_STRIDE) + ko);
                ldm4(b1f, bAddr1 + p * (16 * BS_STRIDE) + ko);
#pragma unroll
                for (int t = 0; t < 2; t++) {
                    mma16816(acc[2 * p + t], af0, b0f[2 * t], b0f[2 * t + 1]);
                    mma16816(acc[2 * p + t], af0, b1f[2 * t], b1f[2 * t + 1]);
                    mma16816(acc[2 * p + t], af1, b0f[2 * t], b0f[2 * t + 1]);
                }
            }
        }
    }
    __syncthreads();   // B ring dead -> Ls overlay

    // ---- spill biased logits: Ls[row][expert], stride 66 ----
    float* Ls = (float*)dyn;
    {
        const int gr = lane >> 2, gc = (lane & 3) * 2;
#pragma unroll
        for (int nt = 0; nt < 8; nt++) {
            int col = nt * 8 + gc;
            int r0 = mrow0 + gr, r1 = mrow0 + gr + 8;
            Ls[(size_t)r0 * LS_STRIDE + col]     = acc[nt][0] + bsh[col];
            Ls[(size_t)r0 * LS_STRIDE + col + 1] = acc[nt][1] + bsh[col + 1];
            Ls[(size_t)r1 * LS_STRIDE + col]     = acc[nt][2] + bsh[col];
            Ls[(size_t)r1 * LS_STRIDE + col + 1] = acc[nt][3] + bsh[col + 1];
        }
    }
    __syncthreads();

    const float NEG_INF = __int_as_float(0xff800000);
    if (tid < BM) {
        const int lrow = tid;
        const int row = row0 + lrow;
        float* L = Ls + (size_t)lrow * LS_STRIDE;
        float mx = L[0];
#pragma unroll
        for (int e = 1; e < E_DIM; e++) mx = fmaxf(mx, L[e]);
        float s = 0.f;
#pragma unroll
        for (int e = 0; e < E_DIM; e++) s += expf(L[e] - mx);
        float inv = 1.f / s;
        // top-9 by raw logits (strict >, lowest index ties)
        float tv[TOPK + 1]; int ti[TOPK + 1];
        unsigned long long used = 0ULL;
#pragma unroll
        for (int j = 0; j < TOPK + 1; j++) {
            float best = NEG_INF; int bi = 0;
            for (int e = 0; e < E_DIM; e++) {
                float v = L[e];
                if (!((used >> e) & 1ULL) && v > best) { best = v; bi = e; }
            }
            used |= (1ULL << bi);
            tv[j] = best; ti[j] = bi;
        }
        bool close = false;
#pragma unroll
        for (int j = 0; j < TOPK; j++)
            close |= (tv[j] - tv[j + 1]) < GAP_TAU;

        int fidx = -1;
        if (close) {
            fidx = atomicAdd(&flagCnt, 1);
            if (fidx < 64) flagList[fidx] = lrow;
        }
        if (!close || fidx >= 64) {
            float gs = 0.f, gv[TOPK];
#pragma unroll
            for (int j = 0; j < TOPK; j++) {
                float g = expf(tv[j] - mx) * inv;
                gv[j] = g; gs += g;
                atomicAdd(&hist[ti[j]], 1);
            }
            float rn = 1.f / (gs + 1e-8f);
#pragma unroll
            for (int j = 0; j < TOPK; j++) {
                out_idx[(size_t)row * TOPK + j]  = (float)ti[j];
                out_gate[(size_t)row * TOPK + j] = gv[j] * rn;
            }
        }
    }
    __syncthreads();

    // ---- exact refine of flagged rows (chunk-256 fp32, ref-matching) ----
    {
        const int nflag = min(flagCnt, 64);
        for (int fi = wid; fi < nflag; fi += 8) {
            const int lrow = flagList[fi];
            const float* xr = x + (size_t)(row0 + lrow) * D_DIM;
            float tot0 = 0.f, tot1 = 0.f;
#pragma unroll 1
            for (int ch = 0; ch < 4; ch++) {
                float s0 = 0.f, s1 = 0.f;
                const float* xp = xr + ch * 256;
                const float* wp = Wt + (size_t)(ch * 256) * E_DIM;
#pragma unroll 4
                for (int k2 = 0; k2 < 256; k2++) {
                    float xvv = __ldg(xp + k2);
                    s0 = fmaf(xvv, __ldg(wp + k2 * E_DIM + lane), s0);
                    s1 = fmaf(xvv, __ldg(wp + k2 * E_DIM + lane + 32), s1);
                }
                if (ch == 0) { tot0 = s0; tot1 = s1; }
                else         { tot0 += s0; tot1 += s1; }
            }
            float* L = Ls + (size_t)lrow * LS_STRIDE;
            L[lane]      = tot0 + bsh[lane];
            L[lane + 32] = tot1 + bsh[lane + 32];
            __syncwarp();
            if (lane == 0) {
                const int row = row0 + lrow;
                float mx = L[0];
                for (int e = 1; e < E_DIM; e++) mx = fmaxf(mx, L[e]);
                float s = 0.f;
                for (int e = 0; e < E_DIM; e++) s += expf(L[e] - mx);
                float inv = 1.f / s;
                unsigned long long used = 0ULL;
                float gs = 0.f, gv[TOPK]; int gi[TOPK];
                for (int j = 0; j < TOPK; j++) {
                    float best = NEG_INF; int bi = 0;
                    for (int e = 0; e < E_DIM; e++) {
                        float v = L[e];
                        if (!((used >> e) & 1ULL) && v > best) { best = v; bi = e; }
                    }
                    used |= (1ULL << bi);
                    float g = expf(best - mx) * inv;
                    gv[j] = g; gi[j] = bi; gs += g;
                    atomicAdd(&hist[bi], 1);
                }
                float rn = 1.f / (gs + 1e-8f);
                for (int j = 0; j < TOPK; j++) {
                    out_idx[(size_t)row * TOPK + j]  = (float)gi[j];
                    out_gate[(size_t)row * TOPK + j] = gv[j] * rn;
                }
            }
            __syncwarp();
        }
    }
    __syncthreads();
    if (tid < E_DIM) atomicAdd(&g_counts[tid], hist[tid]);

    // ---- fused finisher: last CTA computes EMA-usage variance ----
    __syncthreads();
    if (tid == 0) {
        __threadfence();
        int old = atomicAdd(&g_done, 1);
        lastFlag = (old == (int)gridDim.x - 1);
    }
    __syncthreads();
    if (lastFlag && tid == 0) {
        float u[E_DIM];
        float m = 0.f;
        for (int e = 0; e < E_DIM; e++) {
            int c = atomicExch(&g_counts[e], 0);   // read + reset for replay
            u[e] = 0.95f * eu[e] + 0.05f * ((float)c * invN);
            m += u[e];
        }
        m *= (1.f / E_DIM);
        float v = 0.f;
        for (int e = 0; e < E_DIM; e++) {
            float d = u[e] - m;
            v += d * d;
        }
        *out_var = v * (1.f / (E_DIM - 1));   // ddof=1
        atomicExch(&g_done, 0);               // reset for next replay
    }
}

extern "C" void kernel_launch(void* const* d_in, const int* in_sizes, int n_in,
                              void* d_out, int out_size) {
    const float* x  = (const float*)d_in[0];
    const float* W  = (const float*)d_in[1];
    const float* b  = (const float*)d_in[2];
    const float* eu = (const float*)d_in[3];
    const int N = in_sizes[0] / D_DIM;   // 262144

    float* out      = (float*)d_out;
    float* out_idx  = out;                        // [N,8] indices (as float)
    float* out_gate = out + (size_t)N * TOPK;     // [N,8] gates
    float* out_var  = out + (out_size - 1);       // scalar variance

    static int smem_set = 0;
    if (!smem_set) {
        cudaFuncSetAttribute(gate_kernel,
                             cudaFuncAttributeMaxDynamicSharedMemorySize,
                             DYN_SMEM);
        smem_set = 1;
    }

    prep_kernel<<<(E_DIM * D_DIM) / 256, 256>>>(W);
    gate_kernel<<<N / BM, NTHREADS, DYN_SMEM>>>(
        x, b, eu, out_idx, out_gate, out_var, 1.f / (float)N);
}